// round 7
// baseline (speedup 1.0000x reference)
#include <cuda_runtime.h>
#include <cuda_bf16.h>
#include <cuda_fp16.h>
#include <cstdint>

#define NN 50000
#define EE 800000
#define IN_F 128
#define HF 64
#define HEADS 4
#define HC 256            // HEADS*HF
#define NEG_SLOPE 0.2f

// ---------------- device scratch ----------------
__device__ __align__(16) float g_h[(size_t)NN * HC];      // projected features fp32
__device__ __align__(16) __half g_hh[(size_t)NN * HC];    // fp16 shadow for gather
__device__ __align__(16) float g_as[NN * HEADS];
__device__ __align__(16) float g_ad[NN * HEADS];
__device__ __align__(16) float g_mid[(size_t)NN * HF];
__device__ __align__(16) float4 g_w4[EE];                 // per-edge logits -> weights
__device__ __align__(16) __nv_bfloat16 g_Ahi[(size_t)NN * IN_F];
__device__ __align__(16) __nv_bfloat16 g_Alo[(size_t)NN * IN_F];
__device__ __align__(16) __nv_bfloat16 g_Bhi[HC * IN_F];
__device__ __align__(16) __nv_bfloat16 g_Blo[HC * IN_F];
__device__ int   g_deg[NN];
__device__ int   g_rowptr[NN + 1];
__device__ int   g_cursor[NN];
__device__ int   g_csr[EE];
__device__ int   g_is64;

__device__ __forceinline__ float lrelu(float v) { return v > 0.f ? v : NEG_SLOPE * v; }

// ---------------- CSR build ----------------
__global__ void k_flag_init() { g_is64 = 1; }

// zero degrees + SAMPLED dtype detect (4096 strided int64 probes; if the buffer
// is really int32, a combined pair is out of [0,NN) w.p. 1-1/NN per probe).
__global__ void k_prep(const long long* __restrict__ ei) {
    int i = blockIdx.x * blockDim.x + threadIdx.x;
    if (i < NN) g_deg[i] = 0;
    if (i < 4096) {
        long long v = ei[(size_t)i * 195];
        if (v < 0 || v >= NN) g_is64 = 0;
    }
}

__global__ void k_hist(const void* __restrict__ eiv) {
    int e = blockIdx.x * blockDim.x + threadIdx.x;
    if (e < EE) {
        int d = g_is64 ? (int)((const long long*)eiv)[EE + e]
                       : ((const int*)eiv)[EE + e];
        if ((unsigned)d < NN) atomicAdd(&g_deg[d], 1);
    }
}

__global__ void k_scan() {
    __shared__ int sm[1024];
    const int t = threadIdx.x;
    const int CH = (NN + 1023) / 1024;
    const int base = t * CH;
    int s = 0;
    for (int i = 0; i < CH; i++) {
        int idx = base + i;
        if (idx < NN) s += g_deg[idx];
    }
    sm[t] = s;
    __syncthreads();
    for (int off = 1; off < 1024; off <<= 1) {
        int v = (t >= off) ? sm[t - off] : 0;
        __syncthreads();
        sm[t] += v;
        __syncthreads();
    }
    int run = (t > 0) ? sm[t - 1] : 0;
    for (int i = 0; i < CH; i++) {
        int idx = base + i;
        if (idx < NN) { g_rowptr[idx] = run; g_cursor[idx] = run; run += g_deg[idx]; }
    }
    if (t == 0) g_rowptr[NN] = sm[1023];
}

__global__ void k_scatter(const void* __restrict__ eiv) {
    int e = blockIdx.x * blockDim.x + threadIdx.x;
    if (e < EE) {
        int s, d;
        if (g_is64) {
            s = (int)((const long long*)eiv)[e];
            d = (int)((const long long*)eiv)[EE + e];
        } else {
            s = ((const int*)eiv)[e];
            d = ((const int*)eiv)[EE + e];
        }
        if ((unsigned)s < NN && (unsigned)d < NN) {
            int p = atomicAdd(&g_cursor[d], 1);
            g_csr[p] = s;
        }
    }
}

// ---------------- fp32 -> split bf16 conversion ----------------
template <int DST, bool FROM_MID>
__global__ void k_cvt(const float* __restrict__ srcp, int n4) {
    int i = blockIdx.x * blockDim.x + threadIdx.x;
    if (i >= n4) return;
    const float4* src = FROM_MID ? (const float4*)g_mid : (const float4*)srcp;
    __nv_bfloat162* hi = (__nv_bfloat162*)(DST == 0 ? g_Ahi : g_Bhi);
    __nv_bfloat162* lo = (__nv_bfloat162*)(DST == 0 ? g_Alo : g_Blo);
    float4 v = src[i];
    __nv_bfloat16 hx = __float2bfloat16_rn(v.x);
    __nv_bfloat16 hy = __float2bfloat16_rn(v.y);
    __nv_bfloat16 hz = __float2bfloat16_rn(v.z);
    __nv_bfloat16 hw = __float2bfloat16_rn(v.w);
    __nv_bfloat16 lx = __float2bfloat16_rn(v.x - __bfloat162float(hx));
    __nv_bfloat16 ly = __float2bfloat16_rn(v.y - __bfloat162float(hy));
    __nv_bfloat16 lz = __float2bfloat16_rn(v.z - __bfloat162float(hz));
    __nv_bfloat16 lw = __float2bfloat16_rn(v.w - __bfloat162float(hw));
    hi[2 * i]     = __halves2bfloat162(hx, hy);
    hi[2 * i + 1] = __halves2bfloat162(hz, hw);
    lo[2 * i]     = __halves2bfloat162(lx, ly);
    lo[2 * i + 1] = __halves2bfloat162(lz, lw);
}

// ---------------- tensor-core GEMM: g_h[M,256] = A * B^T (split bf16) ----------
__device__ __forceinline__ void mma16816(float* c, const uint32_t* a, uint32_t b0, uint32_t b1) {
    asm volatile(
        "mma.sync.aligned.m16n8k16.row.col.f32.bf16.bf16.f32 "
        "{%0,%1,%2,%3},{%4,%5,%6,%7},{%8,%9},{%0,%1,%2,%3};"
        : "+f"(c[0]), "+f"(c[1]), "+f"(c[2]), "+f"(c[3])
        : "r"(a[0]), "r"(a[1]), "r"(a[2]), "r"(a[3]), "r"(b0), "r"(b1));
}

template <int KF>
__global__ void __launch_bounds__(256) k_mma() {
    __shared__ __align__(16) __nv_bfloat16 Ah[128][40], Al[128][40];
    __shared__ __align__(16) __nv_bfloat16 Bh[128][40], Bl[128][40];
    const int t = threadIdx.x;
    const int bm = blockIdx.x * 128, bn = blockIdx.y * 128;
    const int warp = t >> 5, lane = t & 31;
    const int wr = (warp & 1) * 64, wc = (warp >> 1) * 32;
    const int g = lane >> 2, tg = (lane & 3) * 2;

    float acc[4][4][4];
#pragma unroll
    for (int a = 0; a < 4; a++)
#pragma unroll
        for (int b = 0; b < 4; b++)
#pragma unroll
            for (int c = 0; c < 4; c++) acc[a][b][c] = 0.f;

    for (int k0 = 0; k0 < KF; k0 += 32) {
#pragma unroll
        for (int u = t; u < 512; u += 256) {
            int r = u >> 2, cg = (u & 3) * 8;
            uint4 vh = make_uint4(0, 0, 0, 0), vl = vh;
            int gm = bm + r;
            if (gm < NN) {
                vh = *(const uint4*)&g_Ahi[(size_t)gm * KF + k0 + cg];
                vl = *(const uint4*)&g_Alo[(size_t)gm * KF + k0 + cg];
            }
            *(uint4*)&Ah[r][cg] = vh;
            *(uint4*)&Al[r][cg] = vl;
            *(uint4*)&Bh[r][cg] = *(const uint4*)&g_Bhi[(size_t)(bn + r) * KF + k0 + cg];
            *(uint4*)&Bl[r][cg] = *(const uint4*)&g_Blo[(size_t)(bn + r) * KF + k0 + cg];
        }
        __syncthreads();
#pragma unroll
        for (int kk = 0; kk < 32; kk += 16) {
            uint32_t ah[4][4], al[4][4];
#pragma unroll
            for (int mt = 0; mt < 4; mt++) {
                int r0 = wr + mt * 16 + g;
                ah[mt][0] = *(const uint32_t*)&Ah[r0][kk + tg];
                ah[mt][1] = *(const uint32_t*)&Ah[r0 + 8][kk + tg];
                ah[mt][2] = *(const uint32_t*)&Ah[r0][kk + tg + 8];
                ah[mt][3] = *(const uint32_t*)&Ah[r0 + 8][kk + tg + 8];
                al[mt][0] = *(const uint32_t*)&Al[r0][kk + tg];
                al[mt][1] = *(const uint32_t*)&Al[r0 + 8][kk + tg];
                al[mt][2] = *(const uint32_t*)&Al[r0][kk + tg + 8];
                al[mt][3] = *(const uint32_t*)&Al[r0 + 8][kk + tg + 8];
            }
#pragma unroll
            for (int nt = 0; nt < 4; nt++) {
                int c0 = wc + nt * 8 + g;
                uint32_t bh0 = *(const uint32_t*)&Bh[c0][kk + tg];
                uint32_t bh1 = *(const uint32_t*)&Bh[c0][kk + tg + 8];
                uint32_t bl0 = *(const uint32_t*)&Bl[c0][kk + tg];
                uint32_t bl1 = *(const uint32_t*)&Bl[c0][kk + tg + 8];
#pragma unroll
                for (int mt = 0; mt < 4; mt++) {
                    mma16816(acc[mt][nt], ah[mt], bh0, bh1);
                    mma16816(acc[mt][nt], ah[mt], bl0, bl1);
                    mma16816(acc[mt][nt], al[mt], bh0, bh1);
                }
            }
        }
        __syncthreads();
    }
#pragma unroll
    for (int mt = 0; mt < 4; mt++) {
        int r0 = bm + wr + mt * 16 + g;
#pragma unroll
        for (int nt = 0; nt < 4; nt++) {
            int col = bn + wc + nt * 8 + tg;
            if (r0 < NN)
                *(float2*)&g_h[(size_t)r0 * HC + col] = make_float2(acc[mt][nt][0], acc[mt][nt][1]);
            if (r0 + 8 < NN)
                *(float2*)&g_h[(size_t)(r0 + 8) * HC + col] = make_float2(acc[mt][nt][2], acc[mt][nt][3]);
        }
    }
}

// ---------------- attention coefficients + fp16 pack of h ----------------
__global__ void k_attn_coef(const float* __restrict__ a_src, const float* __restrict__ a_dst) {
    int warp = (blockIdx.x * blockDim.x + threadIdx.x) >> 5;
    if (warp >= NN) return;
    int lane = threadIdx.x & 31;
    const float4* hp = (const float4*)&g_h[(size_t)warp * HC];
    float4 v0 = hp[lane * 2], v1 = hp[lane * 2 + 1];   // channels 8*lane .. 8*lane+7

    // pack fp16 shadow (coalesced 16B per lane)
    union { __half2 h[4]; uint4 u; } P;
    P.h[0] = __floats2half2_rn(v0.x, v0.y);
    P.h[1] = __floats2half2_rn(v0.z, v0.w);
    P.h[2] = __floats2half2_rn(v1.x, v1.y);
    P.h[3] = __floats2half2_rn(v1.z, v1.w);
    *(uint4*)&g_hh[(size_t)warp * HC + 8 * lane] = P.u;

    const float4* ap = (const float4*)a_src;
    const float4* bp = (const float4*)a_dst;
    float4 a0 = ap[lane * 2], a1 = ap[lane * 2 + 1];
    float4 b0 = bp[lane * 2], b1 = bp[lane * 2 + 1];
    float s = v0.x * a0.x + v0.y * a0.y + v0.z * a0.z + v0.w * a0.w
            + v1.x * a1.x + v1.y * a1.y + v1.z * a1.z + v1.w * a1.w;
    float d = v0.x * b0.x + v0.y * b0.y + v0.z * b0.z + v0.w * b0.w
            + v1.x * b1.x + v1.y * b1.y + v1.z * b1.z + v1.w * b1.w;
#pragma unroll
    for (int off = 4; off; off >>= 1) {
        s += __shfl_down_sync(0xffffffffu, s, off);
        d += __shfl_down_sync(0xffffffffu, d, off);
    }
    if ((lane & 7) == 0) {
        int h = lane >> 3;
        g_as[warp * 4 + h] = s;
        g_ad[warp * 4 + h] = d;
    }
}

// ---------------- aggregation ----------------
template <bool TO_OUT>
__global__ void k_aggregate(const float* __restrict__ bias, float* __restrict__ out) {
    int warp = (blockIdx.x * blockDim.x + threadIdx.x) >> 5;
    if (warp >= NN) return;
    const int n = warp;
    const int l = threadIdx.x & 31;
    const int beg = g_rowptr[n];
    const int dr  = g_rowptr[n + 1] - beg;       // real edges; self handled logically
    const float4 adn = *(const float4*)&g_ad[n * 4];
    const float4 asn = *(const float4*)&g_as[n * 4];

    float4 es;  // self-loop logit
    es.x = lrelu(asn.x + adn.x); es.y = lrelu(asn.y + adn.y);
    es.z = lrelu(asn.z + adn.z); es.w = lrelu(asn.w + adn.w);

    // pass A: gather alpha_src once, store logits, track max
    float m0 = es.x, m1 = es.y, m2 = es.z, m3 = es.w;
    for (int i = l; i < dr; i += 32) {
        int s = g_csr[beg + i];
        float4 av = *(const float4*)&g_as[s * 4];
        float4 e;
        e.x = lrelu(av.x + adn.x); e.y = lrelu(av.y + adn.y);
        e.z = lrelu(av.z + adn.z); e.w = lrelu(av.w + adn.w);
        g_w4[beg + i] = e;
        m0 = fmaxf(m0, e.x); m1 = fmaxf(m1, e.y);
        m2 = fmaxf(m2, e.z); m3 = fmaxf(m3, e.w);
    }
#pragma unroll
    for (int off = 16; off; off >>= 1) {
        m0 = fmaxf(m0, __shfl_xor_sync(0xffffffffu, m0, off));
        m1 = fmaxf(m1, __shfl_xor_sync(0xffffffffu, m1, off));
        m2 = fmaxf(m2, __shfl_xor_sync(0xffffffffu, m2, off));
        m3 = fmaxf(m3, __shfl_xor_sync(0xffffffffu, m3, off));
    }
    __syncwarp();

    // pass B: exponentiate in place, accumulate denominator
    float d0 = 0.f, d1 = 0.f, d2 = 0.f, d3 = 0.f;
    for (int i = l; i < dr; i += 32) {
        float4 e = g_w4[beg + i];
        e.x = __expf(e.x - m0); e.y = __expf(e.y - m1);
        e.z = __expf(e.z - m2); e.w = __expf(e.w - m3);
        g_w4[beg + i] = e;
        d0 += e.x; d1 += e.y; d2 += e.z; d3 += e.w;
    }
#pragma unroll
    for (int off = 16; off; off >>= 1) {
        d0 += __shfl_xor_sync(0xffffffffu, d0, off);
        d1 += __shfl_xor_sync(0xffffffffu, d1, off);
        d2 += __shfl_xor_sync(0xffffffffu, d2, off);
        d3 += __shfl_xor_sync(0xffffffffu, d3, off);
    }
    es.x = __expf(es.x - m0); es.y = __expf(es.y - m1);
    es.z = __expf(es.z - m2); es.w = __expf(es.w - m3);
    d0 += es.x; d1 += es.y; d2 += es.z; d3 += es.w;
    const float r0 = 1.f / (d0 + 1e-16f), r1 = 1.f / (d1 + 1e-16f);
    const float r2 = 1.f / (d2 + 1e-16f), r3 = 1.f / (d3 + 1e-16f);
    __syncwarp();

    // pass C: fp16 weighted gather. Lane owns 8 contiguous channels [8l..8l+7],
    // which lie entirely in head l>>3. One LDG.128 per lane per edge.
    const int hd = l >> 3;
    const float rh = (hd == 0) ? r0 : (hd == 1) ? r1 : (hd == 2) ? r2 : r3;
    const int c8 = 8 * l;
    float acc[8];
#pragma unroll
    for (int j = 0; j < 8; j++) acc[j] = 0.f;

#pragma unroll 2
    for (int i = 0; i < dr; i++) {
        int s = g_csr[beg + i];                         // broadcast
        float4 w = g_w4[beg + i];                       // broadcast, sequential
        float wl = ((hd == 0) ? w.x : (hd == 1) ? w.y : (hd == 2) ? w.z : w.w) * rh;
        union { uint4 u; __half2 h[4]; } H;
        H.u = *(const uint4*)&g_hh[(size_t)s * HC + c8];
        float2 f0 = __half22float2(H.h[0]);
        float2 f1 = __half22float2(H.h[1]);
        float2 f2 = __half22float2(H.h[2]);
        float2 f3 = __half22float2(H.h[3]);
        acc[0] = fmaf(wl, f0.x, acc[0]); acc[1] = fmaf(wl, f0.y, acc[1]);
        acc[2] = fmaf(wl, f1.x, acc[2]); acc[3] = fmaf(wl, f1.y, acc[3]);
        acc[4] = fmaf(wl, f2.x, acc[4]); acc[5] = fmaf(wl, f2.y, acc[5]);
        acc[6] = fmaf(wl, f3.x, acc[6]); acc[7] = fmaf(wl, f3.y, acc[7]);
    }
    {   // self loop
        float wl = ((hd == 0) ? es.x : (hd == 1) ? es.y : (hd == 2) ? es.z : es.w) * rh;
        union { uint4 u; __half2 h[4]; } H;
        H.u = *(const uint4*)&g_hh[(size_t)n * HC + c8];
        float2 f0 = __half22float2(H.h[0]);
        float2 f1 = __half22float2(H.h[1]);
        float2 f2 = __half22float2(H.h[2]);
        float2 f3 = __half22float2(H.h[3]);
        acc[0] = fmaf(wl, f0.x, acc[0]); acc[1] = fmaf(wl, f0.y, acc[1]);
        acc[2] = fmaf(wl, f1.x, acc[2]); acc[3] = fmaf(wl, f1.y, acc[3]);
        acc[4] = fmaf(wl, f2.x, acc[4]); acc[5] = fmaf(wl, f2.y, acc[5]);
        acc[6] = fmaf(wl, f3.x, acc[6]); acc[7] = fmaf(wl, f3.y, acc[7]);
    }
    // head combine: lanes l, l^8, l^16, l^24 hold same local channels for heads 0..3
#pragma unroll
    for (int j = 0; j < 8; j++) {
        acc[j] += __shfl_xor_sync(0xffffffffu, acc[j], 8);
        acc[j] += __shfl_xor_sync(0xffffffffu, acc[j], 16);
    }
    if (l < 8) {   // lane l writes output channels 8l..8l+7
        const float4 ba = *(const float4*)&bias[8 * l];
        const float4 bb = *(const float4*)&bias[8 * l + 4];
        float o[8];
#pragma unroll
        for (int j = 0; j < 8; j++) o[j] = acc[j] * 0.25f;
        o[0] += ba.x; o[1] += ba.y; o[2] += ba.z; o[3] += ba.w;
        o[4] += bb.x; o[5] += bb.y; o[6] += bb.z; o[7] += bb.w;
        if (!TO_OUT) {
#pragma unroll
            for (int j = 0; j < 8; j++) o[j] = o[j] > 0.f ? o[j] : expm1f(o[j]);
            *(float4*)&g_mid[(size_t)n * HF + 8 * l]     = make_float4(o[0], o[1], o[2], o[3]);
            *(float4*)&g_mid[(size_t)n * HF + 8 * l + 4] = make_float4(o[4], o[5], o[6], o[7]);
        } else {
            *(float4*)&out[(size_t)n * HF + 8 * l]     = make_float4(o[0], o[1], o[2], o[3]);
            *(float4*)&out[(size_t)n * HF + 8 * l + 4] = make_float4(o[4], o[5], o[6], o[7]);
        }
    }
}

// ---------------- host launcher ----------------
extern "C" void kernel_launch(void* const* d_in, const int* in_sizes, int n_in,
                              void* d_out, int out_size) {
    const float* x   = (const float*)d_in[0];
    const void*  ei  = d_in[1];
    const float* W1  = (const float*)d_in[2];
    const float* as1 = (const float*)d_in[3];
    const float* ad1 = (const float*)d_in[4];
    const float* b1  = (const float*)d_in[5];
    const float* W2  = (const float*)d_in[6];
    const float* as2 = (const float*)d_in[7];
    const float* ad2 = (const float*)d_in[8];
    const float* b2  = (const float*)d_in[9];
    float*       out = (float*)d_out;

    // CSR build
    k_flag_init<<<1, 1>>>();
    k_prep<<<(NN + 255) / 256, 256>>>((const long long*)ei);
    k_hist<<<(EE + 255) / 256, 256>>>(ei);
    k_scan<<<1, 1024>>>();
    k_scatter<<<(EE + 255) / 256, 256>>>(ei);

    const dim3 gemm_grid((NN + 127) / 128, 2);
    const int  warps_grid = (NN * 32 + 255) / 256;

    // layer 1
    {
        int n4a = NN * IN_F / 4, n4b = HC * IN_F / 4;
        k_cvt<0, false><<<(n4a + 255) / 256, 256>>>(x, n4a);
        k_cvt<1, false><<<(n4b + 255) / 256, 256>>>(W1, n4b);
    }
    k_mma<IN_F><<<gemm_grid, 256>>>();
    k_attn_coef<<<warps_grid, 256>>>(as1, ad1);
    k_aggregate<false><<<warps_grid, 256>>>(b1, nullptr);

    // layer 2
    {
        int n4a = NN * HF / 4, n4b = HC * HF / 4;
        k_cvt<0, true><<<(n4a + 255) / 256, 256>>>(nullptr, n4a);
        k_cvt<1, false><<<(n4b + 255) / 256, 256>>>(W2, n4b);
    }
    k_mma<HF><<<gemm_grid, 256>>>();
    k_attn_coef<<<warps_grid, 256>>>(as2, ad2);
    k_aggregate<true><<<warps_grid, 256>>>(b2, out);
}

// round 11
// speedup vs baseline: 1.3639x; 1.3639x over previous
#include <cuda_runtime.h>
#include <cuda_bf16.h>
#include <cuda_fp16.h>
#include <cstdint>

#define NN 50000
#define EE 800000
#define IN_F 128
#define HF 64
#define HEADS 4
#define HC 256            // HEADS*HF
#define NEG_SLOPE 0.2f
#define NBLK ((NN + 255) / 256)   // 196

// ---------------- device scratch ----------------
__device__ __align__(16) float g_h[(size_t)NN * HC];      // projected features fp32
__device__ __align__(16) __half g_hh[(size_t)NN * HC];    // fp16 shadow for gather
__device__ __align__(16) float g_as[NN * HEADS];
__device__ __align__(16) float g_ad[NN * HEADS];
__device__ __align__(16) float g_mid[(size_t)NN * HF];
__device__ __align__(16) float4 g_w4[EE];                 // per-edge logits -> weights
__device__ __align__(16) __nv_bfloat16 g_Ahi[(size_t)NN * IN_F];
__device__ __align__(16) __nv_bfloat16 g_Alo[(size_t)NN * IN_F];
__device__ __align__(16) __nv_bfloat16 g_Bhi[HC * IN_F];
__device__ __align__(16) __nv_bfloat16 g_Blo[HC * IN_F];
__device__ int   g_deg[NN];
__device__ int   g_rowptr[NN + 1];
__device__ int   g_cursor[NN];
__device__ int   g_csr[EE];
__device__ int   g_bsum[256];
__device__ int   g_boff[256];
__device__ int   g_is64;

__device__ __forceinline__ float lrelu(float v) { return v > 0.f ? v : NEG_SLOPE * v; }

// ---------------- CSR build ----------------
__global__ void k_flag_init() { g_is64 = 1; }

// zero degrees + SAMPLED dtype detect (4096 strided int64 probes)
__global__ void k_prep(const long long* __restrict__ ei) {
    int i = blockIdx.x * blockDim.x + threadIdx.x;
    if (i < NN) g_deg[i] = 0;
    if (i < 4096) {
        long long v = ei[(size_t)i * 195];
        if (v < 0 || v >= NN) g_is64 = 0;
    }
}

__global__ void k_hist(const void* __restrict__ eiv) {
    int e = blockIdx.x * blockDim.x + threadIdx.x;
    if (e < EE) {
        int d = g_is64 ? (int)((const long long*)eiv)[EE + e]
                       : ((const int*)eiv)[EE + e];
        if ((unsigned)d < NN) atomicAdd(&g_deg[d], 1);
    }
}

// --- multi-block exclusive scan of g_deg -> g_rowptr/g_cursor ---
__global__ void k_partial() {
    __shared__ int sm[256];
    int i = blockIdx.x * 256 + threadIdx.x;
    int t = threadIdx.x;
    sm[t] = (i < NN) ? g_deg[i] : 0;
    __syncthreads();
#pragma unroll
    for (int off = 128; off; off >>= 1) {
        if (t < off) sm[t] += sm[t + off];
        __syncthreads();
    }
    if (t == 0) g_bsum[blockIdx.x] = sm[0];
}

__global__ void k_scanb() {
    __shared__ int sm[256];
    int t = threadIdx.x;
    int v = (t < NBLK) ? g_bsum[t] : 0;
    sm[t] = v;
    __syncthreads();
#pragma unroll
    for (int off = 1; off < 256; off <<= 1) {
        int x = (t >= off) ? sm[t - off] : 0;
        __syncthreads();
        sm[t] += x;
        __syncthreads();
    }
    if (t < NBLK) g_boff[t] = sm[t] - v;
    if (t == 255) g_rowptr[NN] = sm[255];
}

__global__ void k_write() {
    __shared__ int sm[256];
    int i = blockIdx.x * 256 + threadIdx.x;
    int t = threadIdx.x;
    int v = (i < NN) ? g_deg[i] : 0;
    sm[t] = v;
    __syncthreads();
#pragma unroll
    for (int off = 1; off < 256; off <<= 1) {
        int x = (t >= off) ? sm[t - off] : 0;
        __syncthreads();
        sm[t] += x;
        __syncthreads();
    }
    if (i < NN) {
        int excl = sm[t] - v + g_boff[blockIdx.x];
        g_rowptr[i] = excl;
        g_cursor[i] = excl;
    }
}

__global__ void k_scatter(const void* __restrict__ eiv) {
    int e = blockIdx.x * blockDim.x + threadIdx.x;
    if (e < EE) {
        int s, d;
        if (g_is64) {
            s = (int)((const long long*)eiv)[e];
            d = (int)((const long long*)eiv)[EE + e];
        } else {
            s = ((const int*)eiv)[e];
            d = ((const int*)eiv)[EE + e];
        }
        if ((unsigned)s < NN && (unsigned)d < NN) {
            int p = atomicAdd(&g_cursor[d], 1);
            g_csr[p] = s;
        }
    }
}

// ---------------- fp32 -> split bf16 conversion ----------------
template <int DST, bool FROM_MID>
__global__ void k_cvt(const float* __restrict__ srcp, int n4) {
    int i = blockIdx.x * blockDim.x + threadIdx.x;
    if (i >= n4) return;
    const float4* src = FROM_MID ? (const float4*)g_mid : (const float4*)srcp;
    __nv_bfloat162* hi = (__nv_bfloat162*)(DST == 0 ? g_Ahi : g_Bhi);
    __nv_bfloat162* lo = (__nv_bfloat162*)(DST == 0 ? g_Alo : g_Blo);
    float4 v = src[i];
    __nv_bfloat16 hx = __float2bfloat16_rn(v.x);
    __nv_bfloat16 hy = __float2bfloat16_rn(v.y);
    __nv_bfloat16 hz = __float2bfloat16_rn(v.z);
    __nv_bfloat16 hw = __float2bfloat16_rn(v.w);
    __nv_bfloat16 lx = __float2bfloat16_rn(v.x - __bfloat162float(hx));
    __nv_bfloat16 ly = __float2bfloat16_rn(v.y - __bfloat162float(hy));
    __nv_bfloat16 lz = __float2bfloat16_rn(v.z - __bfloat162float(hz));
    __nv_bfloat16 lw = __float2bfloat16_rn(v.w - __bfloat162float(hw));
    hi[2 * i]     = __halves2bfloat162(hx, hy);
    hi[2 * i + 1] = __halves2bfloat162(hz, hw);
    lo[2 * i]     = __halves2bfloat162(lx, ly);
    lo[2 * i + 1] = __halves2bfloat162(lz, lw);
}

// ---------------- tensor-core GEMM: g_h[M,256] = A * B^T (split bf16) ----------
__device__ __forceinline__ void mma16816(float* c, const uint32_t* a, uint32_t b0, uint32_t b1) {
    asm volatile(
        "mma.sync.aligned.m16n8k16.row.col.f32.bf16.bf16.f32 "
        "{%0,%1,%2,%3},{%4,%5,%6,%7},{%8,%9},{%0,%1,%2,%3};"
        : "+f"(c[0]), "+f"(c[1]), "+f"(c[2]), "+f"(c[3])
        : "r"(a[0]), "r"(a[1]), "r"(a[2]), "r"(a[3]), "r"(b0), "r"(b1));
}

template <int KF>
__global__ void __launch_bounds__(256) k_mma() {
    __shared__ __align__(16) __nv_bfloat16 Ah[128][40], Al[128][40];
    __shared__ __align__(16) __nv_bfloat16 Bh[128][40], Bl[128][40];
    const int t = threadIdx.x;
    const int bm = blockIdx.x * 128, bn = blockIdx.y * 128;
    const int warp = t >> 5, lane = t & 31;
    const int wr = (warp & 1) * 64, wc = (warp >> 1) * 32;
    const int g = lane >> 2, tg = (lane & 3) * 2;

    float acc[4][4][4];
#pragma unroll
    for (int a = 0; a < 4; a++)
#pragma unroll
        for (int b = 0; b < 4; b++)
#pragma unroll
            for (int c = 0; c < 4; c++) acc[a][b][c] = 0.f;

    for (int k0 = 0; k0 < KF; k0 += 32) {
#pragma unroll
        for (int u = t; u < 512; u += 256) {
            int r = u >> 2, cg = (u & 3) * 8;
            uint4 vh = make_uint4(0, 0, 0, 0), vl = vh;
            int gm = bm + r;
            if (gm < NN) {
                vh = *(const uint4*)&g_Ahi[(size_t)gm * KF + k0 + cg];
                vl = *(const uint4*)&g_Alo[(size_t)gm * KF + k0 + cg];
            }
            *(uint4*)&Ah[r][cg] = vh;
            *(uint4*)&Al[r][cg] = vl;
            *(uint4*)&Bh[r][cg] = *(const uint4*)&g_Bhi[(size_t)(bn + r) * KF + k0 + cg];
            *(uint4*)&Bl[r][cg] = *(const uint4*)&g_Blo[(size_t)(bn + r) * KF + k0 + cg];
        }
        __syncthreads();
#pragma unroll
        for (int kk = 0; kk < 32; kk += 16) {
            uint32_t ah[4][4], al[4][4];
#pragma unroll
            for (int mt = 0; mt < 4; mt++) {
                int r0 = wr + mt * 16 + g;
                ah[mt][0] = *(const uint32_t*)&Ah[r0][kk + tg];
                ah[mt][1] = *(const uint32_t*)&Ah[r0 + 8][kk + tg];
                ah[mt][2] = *(const uint32_t*)&Ah[r0][kk + tg + 8];
                ah[mt][3] = *(const uint32_t*)&Ah[r0 + 8][kk + tg + 8];
                al[mt][0] = *(const uint32_t*)&Al[r0][kk + tg];
                al[mt][1] = *(const uint32_t*)&Al[r0 + 8][kk + tg];
                al[mt][2] = *(const uint32_t*)&Al[r0][kk + tg + 8];
                al[mt][3] = *(const uint32_t*)&Al[r0 + 8][kk + tg + 8];
            }
#pragma unroll
            for (int nt = 0; nt < 4; nt++) {
                int c0 = wc + nt * 8 + g;
                uint32_t bh0 = *(const uint32_t*)&Bh[c0][kk + tg];
                uint32_t bh1 = *(const uint32_t*)&Bh[c0][kk + tg + 8];
                uint32_t bl0 = *(const uint32_t*)&Bl[c0][kk + tg];
                uint32_t bl1 = *(const uint32_t*)&Bl[c0][kk + tg + 8];
#pragma unroll
                for (int mt = 0; mt < 4; mt++) {
                    mma16816(acc[mt][nt], ah[mt], bh0, bh1);
                    mma16816(acc[mt][nt], ah[mt], bl0, bl1);
                    mma16816(acc[mt][nt], al[mt], bh0, bh1);
                }
            }
        }
        __syncthreads();
    }
#pragma unroll
    for (int mt = 0; mt < 4; mt++) {
        int r0 = bm + wr + mt * 16 + g;
#pragma unroll
        for (int nt = 0; nt < 4; nt++) {
            int col = bn + wc + nt * 8 + tg;
            if (r0 < NN)
                *(float2*)&g_h[(size_t)r0 * HC + col] = make_float2(acc[mt][nt][0], acc[mt][nt][1]);
            if (r0 + 8 < NN)
                *(float2*)&g_h[(size_t)(r0 + 8) * HC + col] = make_float2(acc[mt][nt][2], acc[mt][nt][3]);
        }
    }
}

// ---------------- attention coefficients + fp16 pack of h ----------------
__global__ void k_attn_coef(const float* __restrict__ a_src, const float* __restrict__ a_dst) {
    int warp = (blockIdx.x * blockDim.x + threadIdx.x) >> 5;
    if (warp >= NN) return;
    int lane = threadIdx.x & 31;
    const float4* hp = (const float4*)&g_h[(size_t)warp * HC];
    float4 v0 = hp[lane * 2], v1 = hp[lane * 2 + 1];   // channels 8*lane .. 8*lane+7

    union { __half2 h[4]; uint4 u; } P;
    P.h[0] = __floats2half2_rn(v0.x, v0.y);
    P.h[1] = __floats2half2_rn(v0.z, v0.w);
    P.h[2] = __floats2half2_rn(v1.x, v1.y);
    P.h[3] = __floats2half2_rn(v1.z, v1.w);
    *(uint4*)&g_hh[(size_t)warp * HC + 8 * lane] = P.u;

    const float4* ap = (const float4*)a_src;
    const float4* bp = (const float4*)a_dst;
    float4 a0 = ap[lane * 2], a1 = ap[lane * 2 + 1];
    float4 b0 = bp[lane * 2], b1 = bp[lane * 2 + 1];
    float s = v0.x * a0.x + v0.y * a0.y + v0.z * a0.z + v0.w * a0.w
            + v1.x * a1.x + v1.y * a1.y + v1.z * a1.z + v1.w * a1.w;
    float d = v0.x * b0.x + v0.y * b0.y + v0.z * b0.z + v0.w * b0.w
            + v1.x * b1.x + v1.y * b1.y + v1.z * b1.z + v1.w * b1.w;
#pragma unroll
    for (int off = 4; off; off >>= 1) {
        s += __shfl_down_sync(0xffffffffu, s, off);
        d += __shfl_down_sync(0xffffffffu, d, off);
    }
    if ((lane & 7) == 0) {
        int h = lane >> 3;
        g_as[warp * 4 + h] = s;
        g_ad[warp * 4 + h] = d;
    }
}

// ---------------- aggregation ----------------
__device__ __forceinline__ void fma8(float* acc, float wl, uint4 u) {
    union { uint4 uu; __half2 h[4]; } H; H.uu = u;
    float2 f0 = __half22float2(H.h[0]);
    float2 f1 = __half22float2(H.h[1]);
    float2 f2 = __half22float2(H.h[2]);
    float2 f3 = __half22float2(H.h[3]);
    acc[0] = fmaf(wl, f0.x, acc[0]); acc[1] = fmaf(wl, f0.y, acc[1]);
    acc[2] = fmaf(wl, f1.x, acc[2]); acc[3] = fmaf(wl, f1.y, acc[3]);
    acc[4] = fmaf(wl, f2.x, acc[4]); acc[5] = fmaf(wl, f2.y, acc[5]);
    acc[6] = fmaf(wl, f3.x, acc[6]); acc[7] = fmaf(wl, f3.y, acc[7]);
}

template <bool TO_OUT>
__global__ void k_aggregate(const float* __restrict__ bias, float* __restrict__ out) {
    int warp = (blockIdx.x * blockDim.x + threadIdx.x) >> 5;
    if (warp >= NN) return;
    const int n = warp;
    const int l = threadIdx.x & 31;
    const int beg = g_rowptr[n];
    const int dr  = g_rowptr[n + 1] - beg;       // real edges; self handled logically
    const float4 adn = *(const float4*)&g_ad[n * 4];
    const float4 asn = *(const float4*)&g_as[n * 4];

    float4 es;  // self-loop logit
    es.x = lrelu(asn.x + adn.x); es.y = lrelu(asn.y + adn.y);
    es.z = lrelu(asn.z + adn.z); es.w = lrelu(asn.w + adn.w);

    // pass A: gather alpha_src once, store logits, track max
    float m0 = es.x, m1 = es.y, m2 = es.z, m3 = es.w;
    for (int i = l; i < dr; i += 32) {
        int s = g_csr[beg + i];
        float4 av = *(const float4*)&g_as[s * 4];
        float4 e;
        e.x = lrelu(av.x + adn.x); e.y = lrelu(av.y + adn.y);
        e.z = lrelu(av.z + adn.z); e.w = lrelu(av.w + adn.w);
        g_w4[beg + i] = e;
        m0 = fmaxf(m0, e.x); m1 = fmaxf(m1, e.y);
        m2 = fmaxf(m2, e.z); m3 = fmaxf(m3, e.w);
    }
#pragma unroll
    for (int off = 16; off; off >>= 1) {
        m0 = fmaxf(m0, __shfl_xor_sync(0xffffffffu, m0, off));
        m1 = fmaxf(m1, __shfl_xor_sync(0xffffffffu, m1, off));
        m2 = fmaxf(m2, __shfl_xor_sync(0xffffffffu, m2, off));
        m3 = fmaxf(m3, __shfl_xor_sync(0xffffffffu, m3, off));
    }
    __syncwarp();

    // pass B: exponentiate in place, accumulate denominator
    float d0 = 0.f, d1 = 0.f, d2 = 0.f, d3 = 0.f;
    for (int i = l; i < dr; i += 32) {
        float4 e = g_w4[beg + i];
        e.x = __expf(e.x - m0); e.y = __expf(e.y - m1);
        e.z = __expf(e.z - m2); e.w = __expf(e.w - m3);
        g_w4[beg + i] = e;
        d0 += e.x; d1 += e.y; d2 += e.z; d3 += e.w;
    }
#pragma unroll
    for (int off = 16; off; off >>= 1) {
        d0 += __shfl_xor_sync(0xffffffffu, d0, off);
        d1 += __shfl_xor_sync(0xffffffffu, d1, off);
        d2 += __shfl_xor_sync(0xffffffffu, d2, off);
        d3 += __shfl_xor_sync(0xffffffffu, d3, off);
    }
    es.x = __expf(es.x - m0); es.y = __expf(es.y - m1);
    es.z = __expf(es.z - m2); es.w = __expf(es.w - m3);
    d0 += es.x; d1 += es.y; d2 += es.z; d3 += es.w;
    const float r0 = 1.f / (d0 + 1e-16f), r1 = 1.f / (d1 + 1e-16f);
    const float r2 = 1.f / (d2 + 1e-16f), r3 = 1.f / (d3 + 1e-16f);
    __syncwarp();

    // pass C: fp16 weighted gather, unrolled x4 for MLP.
    // Lane owns 8 contiguous channels [8l..8l+7] in head l>>3.
    const int hd = l >> 3;
    const float rh = (hd == 0) ? r0 : (hd == 1) ? r1 : (hd == 2) ? r2 : r3;
    const int c8 = 8 * l;
    float acc[8];
#pragma unroll
    for (int j = 0; j < 8; j++) acc[j] = 0.f;

    int i = 0;
    for (; i + 4 <= dr; i += 4) {
        int s0 = g_csr[beg + i + 0], s1 = g_csr[beg + i + 1];
        int s2 = g_csr[beg + i + 2], s3 = g_csr[beg + i + 3];
        float4 w0 = g_w4[beg + i + 0], w1 = g_w4[beg + i + 1];
        float4 w2 = g_w4[beg + i + 2], w3 = g_w4[beg + i + 3];
        uint4 u0 = *(const uint4*)&g_hh[(size_t)s0 * HC + c8];
        uint4 u1 = *(const uint4*)&g_hh[(size_t)s1 * HC + c8];
        uint4 u2 = *(const uint4*)&g_hh[(size_t)s2 * HC + c8];
        uint4 u3 = *(const uint4*)&g_hh[(size_t)s3 * HC + c8];
        float wl0 = ((hd == 0) ? w0.x : (hd == 1) ? w0.y : (hd == 2) ? w0.z : w0.w) * rh;
        float wl1 = ((hd == 0) ? w1.x : (hd == 1) ? w1.y : (hd == 2) ? w1.z : w1.w) * rh;
        float wl2 = ((hd == 0) ? w2.x : (hd == 1) ? w2.y : (hd == 2) ? w2.z : w2.w) * rh;
        float wl3 = ((hd == 0) ? w3.x : (hd == 1) ? w3.y : (hd == 2) ? w3.z : w3.w) * rh;
        fma8(acc, wl0, u0); fma8(acc, wl1, u1);
        fma8(acc, wl2, u2); fma8(acc, wl3, u3);
    }
    for (; i < dr; i++) {
        int s = g_csr[beg + i];
        float4 w = g_w4[beg + i];
        uint4 u = *(const uint4*)&g_hh[(size_t)s * HC + c8];
        float wl = ((hd == 0) ? w.x : (hd == 1) ? w.y : (hd == 2) ? w.z : w.w) * rh;
        fma8(acc, wl, u);
    }
    {   // self loop
        float wl = ((hd == 0) ? es.x : (hd == 1) ? es.y : (hd == 2) ? es.z : es.w) * rh;
        uint4 u = *(const uint4*)&g_hh[(size_t)n * HC + c8];
        fma8(acc, wl, u);
    }
    // head combine: lanes l, l^8, l^16, l^24 hold same local channels for heads 0..3
#pragma unroll
    for (int j = 0; j < 8; j++) {
        acc[j] += __shfl_xor_sync(0xffffffffu, acc[j], 8);
        acc[j] += __shfl_xor_sync(0xffffffffu, acc[j], 16);
    }
    if (l < 8) {   // lane l writes output channels 8l..8l+7
        const float4 ba = *(const float4*)&bias[8 * l];
        const float4 bb = *(const float4*)&bias[8 * l + 4];
        float o[8];
#pragma unroll
        for (int j = 0; j < 8; j++) o[j] = acc[j] * 0.25f;
        o[0] += ba.x; o[1] += ba.y; o[2] += ba.z; o[3] += ba.w;
        o[4] += bb.x; o[5] += bb.y; o[6] += bb.z; o[7] += bb.w;
        if (!TO_OUT) {
#pragma unroll
            for (int j = 0; j < 8; j++) o[j] = o[j] > 0.f ? o[j] : expm1f(o[j]);
            *(float4*)&g_mid[(size_t)n * HF + 8 * l]     = make_float4(o[0], o[1], o[2], o[3]);
            *(float4*)&g_mid[(size_t)n * HF + 8 * l + 4] = make_float4(o[4], o[5], o[6], o[7]);
        } else {
            *(float4*)&out[(size_t)n * HF + 8 * l]     = make_float4(o[0], o[1], o[2], o[3]);
            *(float4*)&out[(size_t)n * HF + 8 * l + 4] = make_float4(o[4], o[5], o[6], o[7]);
        }
    }
}

// ---------------- host launcher ----------------
extern "C" void kernel_launch(void* const* d_in, const int* in_sizes, int n_in,
                              void* d_out, int out_size) {
    const float* x   = (const float*)d_in[0];
    const void*  ei  = d_in[1];
    const float* W1  = (const float*)d_in[2];
    const float* as1 = (const float*)d_in[3];
    const float* ad1 = (const float*)d_in[4];
    const float* b1  = (const float*)d_in[5];
    const float* W2  = (const float*)d_in[6];
    const float* as2 = (const float*)d_in[7];
    const float* ad2 = (const float*)d_in[8];
    const float* b2  = (const float*)d_in[9];
    float*       out = (float*)d_out;

    // CSR build (multi-block scan)
    k_flag_init<<<1, 1>>>();
    k_prep<<<NBLK, 256>>>((const long long*)ei);
    k_hist<<<(EE + 255) / 256, 256>>>(ei);
    k_partial<<<NBLK, 256>>>();
    k_scanb<<<1, 256>>>();
    k_write<<<NBLK, 256>>>();
    k_scatter<<<(EE + 255) / 256, 256>>>(ei);

    const dim3 gemm_grid((NN + 127) / 128, 2);
    const int  warps_grid = (NN * 32 + 255) / 256;

    // layer 1
    {
        int n4a = NN * IN_F / 4, n4b = HC * IN_F / 4;
        k_cvt<0, false><<<(n4a + 255) / 256, 256>>>(x, n4a);
        k_cvt<1, false><<<(n4b + 255) / 256, 256>>>(W1, n4b);
    }
    k_mma<IN_F><<<gemm_grid, 256>>>();
    k_attn_coef<<<warps_grid, 256>>>(as1, ad1);
    k_aggregate<false><<<warps_grid, 256>>>(b1, nullptr);

    // layer 2
    {
        int n4a = NN * HF / 4, n4b = HC * HF / 4;
        k_cvt<0, true><<<(n4a + 255) / 256, 256>>>(nullptr, n4a);
        k_cvt<1, false><<<(n4b + 255) / 256, 256>>>(W2, n4b);
    }
    k_mma<HF><<<gemm_grid, 256>>>();
    k_attn_coef<<<warps_grid, 256>>>(as2, ad2);
    k_aggregate<true><<<warps_grid, 256>>>(b2, out);
}

// round 12
// speedup vs baseline: 1.5110x; 1.1079x over previous
#include <cuda_runtime.h>
#include <cuda_bf16.h>
#include <cuda_fp16.h>
#include <cstdint>

#define NN 50000
#define EE 800000
#define IN_F 128
#define HF 64
#define HEADS 4
#define HC 256            // HEADS*HF
#define NEG_SLOPE 0.2f
#define NBLK ((NN + 255) / 256)   // 196

// ---------------- device scratch ----------------
__device__ __align__(16) __half g_hh[(size_t)NN * HC];    // fp16 features for gather
__device__ __align__(16) float g_as[NN * HEADS];
__device__ __align__(16) float g_ad[NN * HEADS];
__device__ __align__(16) float g_mid[(size_t)NN * HF];
__device__ __align__(16) float4 g_w4[EE];                 // per-edge softmax weights
__device__ __align__(16) __nv_bfloat16 g_Ahi[(size_t)NN * IN_F];
__device__ __align__(16) __nv_bfloat16 g_Alo[(size_t)NN * IN_F];
__device__ __align__(16) __nv_bfloat16 g_Bhi[HC * IN_F];
__device__ __align__(16) __nv_bfloat16 g_Blo[HC * IN_F];
__device__ int   g_deg[NN];
__device__ int   g_rowptr[NN + 1];
__device__ int   g_cursor[NN];
__device__ int   g_csr[EE];
__device__ int   g_bsum[256];
__device__ int   g_boff[256];
__device__ int   g_is64;

__device__ __forceinline__ float lrelu(float v) { return v > 0.f ? v : NEG_SLOPE * v; }

// ---------------- CSR build ----------------
__global__ void k_flag_init() { g_is64 = 1; }

__global__ void k_prep(const long long* __restrict__ ei) {
    int i = blockIdx.x * blockDim.x + threadIdx.x;
    if (i < NN) g_deg[i] = 0;
    if (i < 4096) {
        long long v = ei[(size_t)i * 195];
        if (v < 0 || v >= NN) g_is64 = 0;
    }
}

__global__ void k_hist(const void* __restrict__ eiv) {
    int e = blockIdx.x * blockDim.x + threadIdx.x;
    if (e < EE) {
        int d = g_is64 ? (int)((const long long*)eiv)[EE + e]
                       : ((const int*)eiv)[EE + e];
        if ((unsigned)d < NN) atomicAdd(&g_deg[d], 1);
    }
}

__global__ void k_partial() {
    __shared__ int sm[256];
    int i = blockIdx.x * 256 + threadIdx.x;
    int t = threadIdx.x;
    sm[t] = (i < NN) ? g_deg[i] : 0;
    __syncthreads();
#pragma unroll
    for (int off = 128; off; off >>= 1) {
        if (t < off) sm[t] += sm[t + off];
        __syncthreads();
    }
    if (t == 0) g_bsum[blockIdx.x] = sm[0];
}

__global__ void k_scanb() {
    __shared__ int sm[256];
    int t = threadIdx.x;
    int v = (t < NBLK) ? g_bsum[t] : 0;
    sm[t] = v;
    __syncthreads();
#pragma unroll
    for (int off = 1; off < 256; off <<= 1) {
        int x = (t >= off) ? sm[t - off] : 0;
        __syncthreads();
        sm[t] += x;
        __syncthreads();
    }
    if (t < NBLK) g_boff[t] = sm[t] - v;
    if (t == 255) g_rowptr[NN] = sm[255];
}

__global__ void k_write() {
    __shared__ int sm[256];
    int i = blockIdx.x * 256 + threadIdx.x;
    int t = threadIdx.x;
    int v = (i < NN) ? g_deg[i] : 0;
    sm[t] = v;
    __syncthreads();
#pragma unroll
    for (int off = 1; off < 256; off <<= 1) {
        int x = (t >= off) ? sm[t - off] : 0;
        __syncthreads();
        sm[t] += x;
        __syncthreads();
    }
    if (i < NN) {
        int excl = sm[t] - v + g_boff[blockIdx.x];
        g_rowptr[i] = excl;
        g_cursor[i] = excl;
    }
}

__global__ void k_scatter(const void* __restrict__ eiv) {
    int e = blockIdx.x * blockDim.x + threadIdx.x;
    if (e < EE) {
        int s, d;
        if (g_is64) {
            s = (int)((const long long*)eiv)[e];
            d = (int)((const long long*)eiv)[EE + e];
        } else {
            s = ((const int*)eiv)[e];
            d = ((const int*)eiv)[EE + e];
        }
        if ((unsigned)s < NN && (unsigned)d < NN) {
            int p = atomicAdd(&g_cursor[d], 1);
            g_csr[p] = s;
        }
    }
}

// ---------------- fp32 -> split bf16 conversion ----------------
template <int DST, bool FROM_MID>
__global__ void k_cvt(const float* __restrict__ srcp, int n4) {
    int i = blockIdx.x * blockDim.x + threadIdx.x;
    if (i >= n4) return;
    const float4* src = FROM_MID ? (const float4*)g_mid : (const float4*)srcp;
    __nv_bfloat162* hi = (__nv_bfloat162*)(DST == 0 ? g_Ahi : g_Bhi);
    __nv_bfloat162* lo = (__nv_bfloat162*)(DST == 0 ? g_Alo : g_Blo);
    float4 v = src[i];
    __nv_bfloat16 hx = __float2bfloat16_rn(v.x);
    __nv_bfloat16 hy = __float2bfloat16_rn(v.y);
    __nv_bfloat16 hz = __float2bfloat16_rn(v.z);
    __nv_bfloat16 hw = __float2bfloat16_rn(v.w);
    __nv_bfloat16 lx = __float2bfloat16_rn(v.x - __bfloat162float(hx));
    __nv_bfloat16 ly = __float2bfloat16_rn(v.y - __bfloat162float(hy));
    __nv_bfloat16 lz = __float2bfloat16_rn(v.z - __bfloat162float(hz));
    __nv_bfloat16 lw = __float2bfloat16_rn(v.w - __bfloat162float(hw));
    hi[2 * i]     = __halves2bfloat162(hx, hy);
    hi[2 * i + 1] = __halves2bfloat162(hz, hw);
    lo[2 * i]     = __halves2bfloat162(lx, ly);
    lo[2 * i + 1] = __halves2bfloat162(lz, lw);
}

// ---------------- tensor-core GEMM + fused alpha/fp16 epilogue ----------------
// g_hh[M,256] = fp16(A*B^T); g_as/g_ad[M,4] = per-head dots with a_src/a_dst.
__device__ __forceinline__ void mma16816(float* c, const uint32_t* a, uint32_t b0, uint32_t b1) {
    asm volatile(
        "mma.sync.aligned.m16n8k16.row.col.f32.bf16.bf16.f32 "
        "{%0,%1,%2,%3},{%4,%5,%6,%7},{%8,%9},{%0,%1,%2,%3};"
        : "+f"(c[0]), "+f"(c[1]), "+f"(c[2]), "+f"(c[3])
        : "r"(a[0]), "r"(a[1]), "r"(a[2]), "r"(a[3]), "r"(b0), "r"(b1));
}

template <int KF>
__global__ void __launch_bounds__(256) k_mma(const float* __restrict__ a_src,
                                             const float* __restrict__ a_dst) {
    __shared__ __align__(16) __nv_bfloat16 Ah[128][40], Al[128][40];
    __shared__ __align__(16) __nv_bfloat16 Bh[128][40], Bl[128][40];
    __shared__ float as_s[128], ad_s[128];
    __shared__ float part_as[8][64], part_ad[8][64];
    const int t = threadIdx.x;
    const int bm = blockIdx.x * 128, bn = blockIdx.y * 128;
    const int warp = t >> 5, lane = t & 31;
    const int wr = (warp & 1) * 64, wc = (warp >> 1) * 32;
    const int g = lane >> 2, tg = (lane & 3) * 2;

    if (t < 128) {                      // attention vectors for this block's 128 cols
        as_s[t] = a_src[bn + t];
        ad_s[t] = a_dst[bn + t];
    }

    float acc[4][4][4];
#pragma unroll
    for (int a = 0; a < 4; a++)
#pragma unroll
        for (int b = 0; b < 4; b++)
#pragma unroll
            for (int c = 0; c < 4; c++) acc[a][b][c] = 0.f;

    for (int k0 = 0; k0 < KF; k0 += 32) {
#pragma unroll
        for (int u = t; u < 512; u += 256) {
            int r = u >> 2, cg = (u & 3) * 8;
            uint4 vh = make_uint4(0, 0, 0, 0), vl = vh;
            int gm = bm + r;
            if (gm < NN) {
                vh = *(const uint4*)&g_Ahi[(size_t)gm * KF + k0 + cg];
                vl = *(const uint4*)&g_Alo[(size_t)gm * KF + k0 + cg];
            }
            *(uint4*)&Ah[r][cg] = vh;
            *(uint4*)&Al[r][cg] = vl;
            *(uint4*)&Bh[r][cg] = *(const uint4*)&g_Bhi[(size_t)(bn + r) * KF + k0 + cg];
            *(uint4*)&Bl[r][cg] = *(const uint4*)&g_Blo[(size_t)(bn + r) * KF + k0 + cg];
        }
        __syncthreads();
#pragma unroll
        for (int kk = 0; kk < 32; kk += 16) {
            uint32_t ah[4][4], al[4][4];
#pragma unroll
            for (int mt = 0; mt < 4; mt++) {
                int r0 = wr + mt * 16 + g;
                ah[mt][0] = *(const uint32_t*)&Ah[r0][kk + tg];
                ah[mt][1] = *(const uint32_t*)&Ah[r0 + 8][kk + tg];
                ah[mt][2] = *(const uint32_t*)&Ah[r0][kk + tg + 8];
                ah[mt][3] = *(const uint32_t*)&Ah[r0 + 8][kk + tg + 8];
                al[mt][0] = *(const uint32_t*)&Al[r0][kk + tg];
                al[mt][1] = *(const uint32_t*)&Al[r0 + 8][kk + tg];
                al[mt][2] = *(const uint32_t*)&Al[r0][kk + tg + 8];
                al[mt][3] = *(const uint32_t*)&Al[r0 + 8][kk + tg + 8];
            }
#pragma unroll
            for (int nt = 0; nt < 4; nt++) {
                int c0 = wc + nt * 8 + g;
                uint32_t bh0 = *(const uint32_t*)&Bh[c0][kk + tg];
                uint32_t bh1 = *(const uint32_t*)&Bh[c0][kk + tg + 8];
                uint32_t bl0 = *(const uint32_t*)&Bl[c0][kk + tg];
                uint32_t bl1 = *(const uint32_t*)&Bl[c0][kk + tg + 8];
#pragma unroll
                for (int mt = 0; mt < 4; mt++) {
                    mma16816(acc[mt][nt], ah[mt], bh0, bh1);
                    mma16816(acc[mt][nt], ah[mt], bl0, bl1);
                    mma16816(acc[mt][nt], al[mt], bh0, bh1);
                }
            }
        }
        __syncthreads();
    }

    // ---- epilogue: fp16 store + per-row alpha partials ----
#pragma unroll
    for (int mt = 0; mt < 4; mt++) {
        int r0 = bm + wr + mt * 16 + g;
        float pa0 = 0.f, pd0 = 0.f, pa8 = 0.f, pd8 = 0.f;
#pragma unroll
        for (int nt = 0; nt < 4; nt++) {
            int lc = wc + nt * 8 + tg;
            float s0 = as_s[lc], s1 = as_s[lc + 1];
            float d0v = ad_s[lc], d1v = ad_s[lc + 1];
            pa0 = fmaf(acc[mt][nt][0], s0, fmaf(acc[mt][nt][1], s1, pa0));
            pd0 = fmaf(acc[mt][nt][0], d0v, fmaf(acc[mt][nt][1], d1v, pd0));
            pa8 = fmaf(acc[mt][nt][2], s0, fmaf(acc[mt][nt][3], s1, pa8));
            pd8 = fmaf(acc[mt][nt][2], d0v, fmaf(acc[mt][nt][3], d1v, pd8));
            if (r0 < NN)
                *(__half2*)&g_hh[(size_t)r0 * HC + bn + lc] =
                    __floats2half2_rn(acc[mt][nt][0], acc[mt][nt][1]);
            if (r0 + 8 < NN)
                *(__half2*)&g_hh[(size_t)(r0 + 8) * HC + bn + lc] =
                    __floats2half2_rn(acc[mt][nt][2], acc[mt][nt][3]);
        }
        // reduce over the 4 lanes sharing this row (lane&3)
#pragma unroll
        for (int off = 1; off < 4; off <<= 1) {
            pa0 += __shfl_xor_sync(0xffffffffu, pa0, off);
            pd0 += __shfl_xor_sync(0xffffffffu, pd0, off);
            pa8 += __shfl_xor_sync(0xffffffffu, pa8, off);
            pd8 += __shfl_xor_sync(0xffffffffu, pd8, off);
        }
        if ((lane & 3) == 0) {
            int rl = mt * 16 + g;
            part_as[warp][rl]     = pa0;
            part_as[warp][rl + 8] = pa8;
            part_ad[warp][rl]     = pd0;
            part_ad[warp][rl + 8] = pd8;
        }
    }
    __syncthreads();
    // combine: warps {p, p+2} cover head hl=0; {p+4, p+6} head hl=1 (p = row>=64)
    {
        int r  = t & 127;            // local row
        int hl = t >> 7;             // local head 0/1
        int p  = (r >= 64) ? 1 : 0;
        int rl = r & 63;
        int w0 = p + hl * 4, w1 = p + 2 + hl * 4;
        if (bm + r < NN) {
            int hg = (bn >> 6) + hl;     // global head
            g_as[(bm + r) * 4 + hg] = part_as[w0][rl] + part_as[w1][rl];
            g_ad[(bm + r) * 4 + hg] = part_ad[w0][rl] + part_ad[w1][rl];
        }
    }
}

// ---------------- aggregation ----------------
__device__ __forceinline__ void fma8(float* acc, float wl, uint4 u) {
    union { uint4 uu; __half2 h[4]; } H; H.uu = u;
    float2 f0 = __half22float2(H.h[0]);
    float2 f1 = __half22float2(H.h[1]);
    float2 f2 = __half22float2(H.h[2]);
    float2 f3 = __half22float2(H.h[3]);
    acc[0] = fmaf(wl, f0.x, acc[0]); acc[1] = fmaf(wl, f0.y, acc[1]);
    acc[2] = fmaf(wl, f1.x, acc[2]); acc[3] = fmaf(wl, f1.y, acc[3]);
    acc[4] = fmaf(wl, f2.x, acc[4]); acc[5] = fmaf(wl, f2.y, acc[5]);
    acc[6] = fmaf(wl, f3.x, acc[6]); acc[7] = fmaf(wl, f3.y, acc[7]);
}

template <bool TO_OUT>
__global__ void k_aggregate(const float* __restrict__ bias, float* __restrict__ out) {
    int warp = (blockIdx.x * blockDim.x + threadIdx.x) >> 5;
    if (warp >= NN) return;
    const int n = warp;
    const int l = threadIdx.x & 31;
    const int beg = g_rowptr[n];
    const int dr  = g_rowptr[n + 1] - beg;       // real edges; self handled logically
    const float4 adn = *(const float4*)&g_ad[n * 4];
    const float4 asn = *(const float4*)&g_as[n * 4];

    // self-loop weight (no max-shift needed: logits are O(1) bounded)
    float4 ws;
    ws.x = __expf(lrelu(asn.x + adn.x)); ws.y = __expf(lrelu(asn.y + adn.y));
    ws.z = __expf(lrelu(asn.z + adn.z)); ws.w = __expf(lrelu(asn.w + adn.w));

    // fused pass A+B: gather alpha_src, exponentiate, store weight, accumulate denom
    float d0 = 0.f, d1 = 0.f, d2 = 0.f, d3 = 0.f;
    for (int i = l; i < dr; i += 32) {
        int s = g_csr[beg + i];
        float4 av = *(const float4*)&g_as[s * 4];
        float4 w;
        w.x = __expf(lrelu(av.x + adn.x)); w.y = __expf(lrelu(av.y + adn.y));
        w.z = __expf(lrelu(av.z + adn.z)); w.w = __expf(lrelu(av.w + adn.w));
        g_w4[beg + i] = w;
        d0 += w.x; d1 += w.y; d2 += w.z; d3 += w.w;
    }
#pragma unroll
    for (int off = 16; off; off >>= 1) {
        d0 += __shfl_xor_sync(0xffffffffu, d0, off);
        d1 += __shfl_xor_sync(0xffffffffu, d1, off);
        d2 += __shfl_xor_sync(0xffffffffu, d2, off);
        d3 += __shfl_xor_sync(0xffffffffu, d3, off);
    }
    d0 += ws.x; d1 += ws.y; d2 += ws.z; d3 += ws.w;
    const float r0 = 1.f / (d0 + 1e-16f), r1 = 1.f / (d1 + 1e-16f);
    const float r2 = 1.f / (d2 + 1e-16f), r3 = 1.f / (d3 + 1e-16f);
    __syncwarp();

    // pass C: fp16 weighted gather, unrolled x4 for MLP.
    const int hd = l >> 3;
    const float rh = (hd == 0) ? r0 : (hd == 1) ? r1 : (hd == 2) ? r2 : r3;
    const int c8 = 8 * l;
    float acc[8];
#pragma unroll
    for (int j = 0; j < 8; j++) acc[j] = 0.f;

    int i = 0;
    for (; i + 4 <= dr; i += 4) {
        int s0 = g_csr[beg + i + 0], s1 = g_csr[beg + i + 1];
        int s2 = g_csr[beg + i + 2], s3 = g_csr[beg + i + 3];
        float4 w0 = g_w4[beg + i + 0], w1 = g_w4[beg + i + 1];
        float4 w2 = g_w4[beg + i + 2], w3 = g_w4[beg + i + 3];
        uint4 u0 = *(const uint4*)&g_hh[(size_t)s0 * HC + c8];
        uint4 u1 = *(const uint4*)&g_hh[(size_t)s1 * HC + c8];
        uint4 u2 = *(const uint4*)&g_hh[(size_t)s2 * HC + c8];
        uint4 u3 = *(const uint4*)&g_hh[(size_t)s3 * HC + c8];
        float wl0 = ((hd == 0) ? w0.x : (hd == 1) ? w0.y : (hd == 2) ? w0.z : w0.w) * rh;
        float wl1 = ((hd == 0) ? w1.x : (hd == 1) ? w1.y : (hd == 2) ? w1.z : w1.w) * rh;
        float wl2 = ((hd == 0) ? w2.x : (hd == 1) ? w2.y : (hd == 2) ? w2.z : w2.w) * rh;
        float wl3 = ((hd == 0) ? w3.x : (hd == 1) ? w3.y : (hd == 2) ? w3.z : w3.w) * rh;
        fma8(acc, wl0, u0); fma8(acc, wl1, u1);
        fma8(acc, wl2, u2); fma8(acc, wl3, u3);
    }
    for (; i < dr; i++) {
        int s = g_csr[beg + i];
        float4 w = g_w4[beg + i];
        uint4 u = *(const uint4*)&g_hh[(size_t)s * HC + c8];
        float wl = ((hd == 0) ? w.x : (hd == 1) ? w.y : (hd == 2) ? w.z : w.w) * rh;
        fma8(acc, wl, u);
    }
    {   // self loop
        float wl = ((hd == 0) ? ws.x : (hd == 1) ? ws.y : (hd == 2) ? ws.z : ws.w) * rh;
        uint4 u = *(const uint4*)&g_hh[(size_t)n * HC + c8];
        fma8(acc, wl, u);
    }
#pragma unroll
    for (int j = 0; j < 8; j++) {
        acc[j] += __shfl_xor_sync(0xffffffffu, acc[j], 8);
        acc[j] += __shfl_xor_sync(0xffffffffu, acc[j], 16);
    }
    if (l < 8) {
        const float4 ba = *(const float4*)&bias[8 * l];
        const float4 bb = *(const float4*)&bias[8 * l + 4];
        float o[8];
#pragma unroll
        for (int j = 0; j < 8; j++) o[j] = acc[j] * 0.25f;
        o[0] += ba.x; o[1] += ba.y; o[2] += ba.z; o[3] += ba.w;
        o[4] += bb.x; o[5] += bb.y; o[6] += bb.z; o[7] += bb.w;
        if (!TO_OUT) {
#pragma unroll
            for (int j = 0; j < 8; j++) o[j] = o[j] > 0.f ? o[j] : expm1f(o[j]);
            *(float4*)&g_mid[(size_t)n * HF + 8 * l]     = make_float4(o[0], o[1], o[2], o[3]);
            *(float4*)&g_mid[(size_t)n * HF + 8 * l + 4] = make_float4(o[4], o[5], o[6], o[7]);
        } else {
            *(float4*)&out[(size_t)n * HF + 8 * l]     = make_float4(o[0], o[1], o[2], o[3]);
            *(float4*)&out[(size_t)n * HF + 8 * l + 4] = make_float4(o[4], o[5], o[6], o[7]);
        }
    }
}

// ---------------- host launcher ----------------
extern "C" void kernel_launch(void* const* d_in, const int* in_sizes, int n_in,
                              void* d_out, int out_size) {
    const float* x   = (const float*)d_in[0];
    const void*  ei  = d_in[1];
    const float* W1  = (const float*)d_in[2];
    const float* as1 = (const float*)d_in[3];
    const float* ad1 = (const float*)d_in[4];
    const float* b1  = (const float*)d_in[5];
    const float* W2  = (const float*)d_in[6];
    const float* as2 = (const float*)d_in[7];
    const float* ad2 = (const float*)d_in[8];
    const float* b2  = (const float*)d_in[9];
    float*       out = (float*)d_out;

    // CSR build (multi-block scan)
    k_flag_init<<<1, 1>>>();
    k_prep<<<NBLK, 256>>>((const long long*)ei);
    k_hist<<<(EE + 255) / 256, 256>>>(ei);
    k_partial<<<NBLK, 256>>>();
    k_scanb<<<1, 256>>>();
    k_write<<<NBLK, 256>>>();
    k_scatter<<<(EE + 255) / 256, 256>>>(ei);

    const dim3 gemm_grid((NN + 127) / 128, 2);
    const int  warps_grid = (NN * 32 + 255) / 256;

    // layer 1
    {
        int n4a = NN * IN_F / 4, n4b = HC * IN_F / 4;
        k_cvt<0, false><<<(n4a + 255) / 256, 256>>>(x, n4a);
        k_cvt<1, false><<<(n4b + 255) / 256, 256>>>(W1, n4b);
    }
    k_mma<IN_F><<<gemm_grid, 256>>>(as1, ad1);
    k_aggregate<false><<<warps_grid, 256>>>(b1, nullptr);

    // layer 2
    {
        int n4a = NN * HF / 4, n4b = HC * HF / 4;
        k_cvt<0, true><<<(n4a + 255) / 256, 256>>>(nullptr, n4a);
        k_cvt<1, false><<<(n4b + 255) / 256, 256>>>(W2, n4b);
    }
    k_mma<HF><<<gemm_grid, 256>>>(as2, ad2);
    k_aggregate<true><<<warps_grid, 256>>>(b2, out);
}

// round 13
// speedup vs baseline: 1.6510x; 1.0927x over previous
#include <cuda_runtime.h>
#include <cuda_bf16.h>
#include <cuda_fp16.h>
#include <cstdint>

#define NN 50000
#define EE 800000
#define IN_F 128
#define HF 64
#define HEADS 4
#define HC 256            // HEADS*HF
#define NEG_SLOPE 0.2f
#define NBLK ((NN + 255) / 256)       // 196
#define HIST_BLOCKS ((EE + 255) / 256)  // 3125
#define XCVT_BLOCKS ((NN * IN_F / 4 + 255) / 256)  // 6250
#define GEMM_BLOCKS (((NN + 127) / 128) * 2)       // 782

// ---------------- device scratch ----------------
__device__ __align__(16) __half g_hh[(size_t)NN * HC];    // fp16 features for gather
__device__ __align__(16) float g_as[NN * HEADS];
__device__ __align__(16) float g_ad[NN * HEADS];
__device__ __align__(16) float4 g_w4[EE];                 // per-edge softmax weights
__device__ __align__(16) __nv_bfloat16 g_Ahi[(size_t)NN * IN_F];
__device__ __align__(16) __nv_bfloat16 g_Alo[(size_t)NN * IN_F];
__device__ __align__(16) __nv_bfloat16 g_B1hi[HC * IN_F];
__device__ __align__(16) __nv_bfloat16 g_B1lo[HC * IN_F];
__device__ __align__(16) __nv_bfloat16 g_B2hi[HC * HF];
__device__ __align__(16) __nv_bfloat16 g_B2lo[HC * HF];
__device__ int   g_deg[NN];
__device__ int   g_rowptr[NN + 1];
__device__ int   g_cursor[NN];
__device__ int   g_csr[EE];
__device__ int   g_bsum[256];
__device__ int   g_boff[256];
__device__ int   g_is64 = 1;   // static init; probes only ever write 0 (deterministic)

__device__ __forceinline__ float lrelu(float v) { return v > 0.f ? v : NEG_SLOPE * v; }

// convert one float4 (4 values) into split bf16 at element index 4*i
__device__ __forceinline__ void cvt4(float4 v, __nv_bfloat16* hi, __nv_bfloat16* lo, int i) {
    __nv_bfloat16 hx = __float2bfloat16_rn(v.x);
    __nv_bfloat16 hy = __float2bfloat16_rn(v.y);
    __nv_bfloat16 hz = __float2bfloat16_rn(v.z);
    __nv_bfloat16 hw = __float2bfloat16_rn(v.w);
    __nv_bfloat16 lx = __float2bfloat16_rn(v.x - __bfloat162float(hx));
    __nv_bfloat16 ly = __float2bfloat16_rn(v.y - __bfloat162float(hy));
    __nv_bfloat16 lz = __float2bfloat16_rn(v.z - __bfloat162float(hz));
    __nv_bfloat16 lw = __float2bfloat16_rn(v.w - __bfloat162float(hw));
    ((__nv_bfloat162*)hi)[2 * i]     = __halves2bfloat162(hx, hy);
    ((__nv_bfloat162*)hi)[2 * i + 1] = __halves2bfloat162(hz, hw);
    ((__nv_bfloat162*)lo)[2 * i]     = __halves2bfloat162(lx, ly);
    ((__nv_bfloat162*)lo)[2 * i + 1] = __halves2bfloat162(lz, lw);
}

// ---------------- CSR build (+ fused weight conversion) ----------------
__global__ void k_prep(const long long* __restrict__ ei,
                       const float* __restrict__ W1, const float* __restrict__ W2) {
    int i = blockIdx.x * blockDim.x + threadIdx.x;
    if (i < NN) g_deg[i] = 0;
    if (i < 4096) {                       // sampled dtype probe
        long long v = ei[(size_t)i * 195];
        if (v < 0 || v >= NN) g_is64 = 0;
    }
    if (i < HC * IN_F / 4) cvt4(((const float4*)W1)[i], g_B1hi, g_B1lo, i);
    if (i < HC * HF / 4)   cvt4(((const float4*)W2)[i], g_B2hi, g_B2lo, i);
}

// histogram (blocks [0,HIST_BLOCKS)) + x -> split bf16 (remaining blocks)
__global__ void k_hist_cvt(const void* __restrict__ eiv, const float* __restrict__ x) {
    if (blockIdx.x < HIST_BLOCKS) {
        int e = blockIdx.x * 256 + threadIdx.x;
        if (e < EE) {
            int d = g_is64 ? (int)((const long long*)eiv)[EE + e]
                           : ((const int*)eiv)[EE + e];
            if ((unsigned)d < NN) atomicAdd(&g_deg[d], 1);
        }
    } else {
        int i = (blockIdx.x - HIST_BLOCKS) * 256 + threadIdx.x;
        if (i < NN * IN_F / 4) cvt4(((const float4*)x)[i], g_Ahi, g_Alo, i);
    }
}

__global__ void k_partial() {
    __shared__ int sm[256];
    int i = blockIdx.x * 256 + threadIdx.x;
    int t = threadIdx.x;
    sm[t] = (i < NN) ? g_deg[i] : 0;
    __syncthreads();
#pragma unroll
    for (int off = 128; off; off >>= 1) {
        if (t < off) sm[t] += sm[t + off];
        __syncthreads();
    }
    if (t == 0) g_bsum[blockIdx.x] = sm[0];
}

__global__ void k_scanb() {
    __shared__ int sm[256];
    int t = threadIdx.x;
    int v = (t < NBLK) ? g_bsum[t] : 0;
    sm[t] = v;
    __syncthreads();
#pragma unroll
    for (int off = 1; off < 256; off <<= 1) {
        int x = (t >= off) ? sm[t - off] : 0;
        __syncthreads();
        sm[t] += x;
        __syncthreads();
    }
    if (t < NBLK) g_boff[t] = sm[t] - v;
    if (t == 255) g_rowptr[NN] = sm[255];
}

__global__ void k_write() {
    __shared__ int sm[256];
    int i = blockIdx.x * 256 + threadIdx.x;
    int t = threadIdx.x;
    int v = (i < NN) ? g_deg[i] : 0;
    sm[t] = v;
    __syncthreads();
#pragma unroll
    for (int off = 1; off < 256; off <<= 1) {
        int x = (t >= off) ? sm[t - off] : 0;
        __syncthreads();
        sm[t] += x;
        __syncthreads();
    }
    if (i < NN) {
        int excl = sm[t] - v + g_boff[blockIdx.x];
        g_rowptr[i] = excl;
        g_cursor[i] = excl;
    }
}

// ---------------- tensor-core GEMM + fused alpha/fp16 epilogue ----------------
// blocks [0, GEMM_BLOCKS): g_hh = fp16(A*B^T), g_as/g_ad = per-head alpha dots.
// FUSE_SCATTER: blocks [GEMM_BLOCKS, +HIST_BLOCKS) run the CSR scatter concurrently.
__device__ __forceinline__ void mma16816(float* c, const uint32_t* a, uint32_t b0, uint32_t b1) {
    asm volatile(
        "mma.sync.aligned.m16n8k16.row.col.f32.bf16.bf16.f32 "
        "{%0,%1,%2,%3},{%4,%5,%6,%7},{%8,%9},{%0,%1,%2,%3};"
        : "+f"(c[0]), "+f"(c[1]), "+f"(c[2]), "+f"(c[3])
        : "r"(a[0]), "r"(a[1]), "r"(a[2]), "r"(a[3]), "r"(b0), "r"(b1));
}

template <int KF, int LAYER, bool FUSE_SCATTER>
__global__ void __launch_bounds__(256) k_mma(const float* __restrict__ a_src,
                                             const float* __restrict__ a_dst,
                                             const void* __restrict__ eiv) {
    __shared__ __align__(16) __nv_bfloat16 Ah[128][40], Al[128][40];
    __shared__ __align__(16) __nv_bfloat16 Bh[128][40], Bl[128][40];
    __shared__ float as_s[128], ad_s[128];
    __shared__ float part_as[8][64], part_ad[8][64];

    if (FUSE_SCATTER && blockIdx.x >= GEMM_BLOCKS) {     // concurrent CSR scatter
        int e = (blockIdx.x - GEMM_BLOCKS) * 256 + threadIdx.x;
        if (e < EE) {
            int s, d;
            if (g_is64) {
                s = (int)((const long long*)eiv)[e];
                d = (int)((const long long*)eiv)[EE + e];
            } else {
                s = ((const int*)eiv)[e];
                d = ((const int*)eiv)[EE + e];
            }
            if ((unsigned)s < NN && (unsigned)d < NN) {
                int p = atomicAdd(&g_cursor[d], 1);
                g_csr[p] = s;
            }
        }
        return;
    }

    const __nv_bfloat16* Bhi = (LAYER == 1) ? g_B1hi : g_B2hi;
    const __nv_bfloat16* Blo = (LAYER == 1) ? g_B1lo : g_B2lo;
    const int t = threadIdx.x;
    const int bm = (blockIdx.x >> 1) * 128, bn = (blockIdx.x & 1) * 128;
    const int warp = t >> 5, lane = t & 31;
    const int wr = (warp & 1) * 64, wc = (warp >> 1) * 32;
    const int g = lane >> 2, tg = (lane & 3) * 2;

    if (t < 128) {
        as_s[t] = a_src[bn + t];
        ad_s[t] = a_dst[bn + t];
    }

    float acc[4][4][4];
#pragma unroll
    for (int a = 0; a < 4; a++)
#pragma unroll
        for (int b = 0; b < 4; b++)
#pragma unroll
            for (int c = 0; c < 4; c++) acc[a][b][c] = 0.f;

    for (int k0 = 0; k0 < KF; k0 += 32) {
#pragma unroll
        for (int u = t; u < 512; u += 256) {
            int r = u >> 2, cg = (u & 3) * 8;
            uint4 vh = make_uint4(0, 0, 0, 0), vl = vh;
            int gm = bm + r;
            if (gm < NN) {
                vh = *(const uint4*)&g_Ahi[(size_t)gm * KF + k0 + cg];
                vl = *(const uint4*)&g_Alo[(size_t)gm * KF + k0 + cg];
            }
            *(uint4*)&Ah[r][cg] = vh;
            *(uint4*)&Al[r][cg] = vl;
            *(uint4*)&Bh[r][cg] = *(const uint4*)&Bhi[(size_t)(bn + r) * KF + k0 + cg];
            *(uint4*)&Bl[r][cg] = *(const uint4*)&Blo[(size_t)(bn + r) * KF + k0 + cg];
        }
        __syncthreads();
#pragma unroll
        for (int kk = 0; kk < 32; kk += 16) {
            uint32_t ah[4][4], al[4][4];
#pragma unroll
            for (int mt = 0; mt < 4; mt++) {
                int r0 = wr + mt * 16 + g;
                ah[mt][0] = *(const uint32_t*)&Ah[r0][kk + tg];
                ah[mt][1] = *(const uint32_t*)&Ah[r0 + 8][kk + tg];
                ah[mt][2] = *(const uint32_t*)&Ah[r0][kk + tg + 8];
                ah[mt][3] = *(const uint32_t*)&Ah[r0 + 8][kk + tg + 8];
                al[mt][0] = *(const uint32_t*)&Al[r0][kk + tg];
                al[mt][1] = *(const uint32_t*)&Al[r0 + 8][kk + tg];
                al[mt][2] = *(const uint32_t*)&Al[r0][kk + tg + 8];
                al[mt][3] = *(const uint32_t*)&Al[r0 + 8][kk + tg + 8];
            }
#pragma unroll
            for (int nt = 0; nt < 4; nt++) {
                int c0 = wc + nt * 8 + g;
                uint32_t bh0 = *(const uint32_t*)&Bh[c0][kk + tg];
                uint32_t bh1 = *(const uint32_t*)&Bh[c0][kk + tg + 8];
                uint32_t bl0 = *(const uint32_t*)&Bl[c0][kk + tg];
                uint32_t bl1 = *(const uint32_t*)&Bl[c0][kk + tg + 8];
#pragma unroll
                for (int mt = 0; mt < 4; mt++) {
                    mma16816(acc[mt][nt], ah[mt], bh0, bh1);
                    mma16816(acc[mt][nt], ah[mt], bl0, bl1);
                    mma16816(acc[mt][nt], al[mt], bh0, bh1);
                }
            }
        }
        __syncthreads();
    }

    // ---- epilogue: fp16 store + per-row alpha partials ----
#pragma unroll
    for (int mt = 0; mt < 4; mt++) {
        int r0 = bm + wr + mt * 16 + g;
        float pa0 = 0.f, pd0 = 0.f, pa8 = 0.f, pd8 = 0.f;
#pragma unroll
        for (int nt = 0; nt < 4; nt++) {
            int lc = wc + nt * 8 + tg;
            float s0 = as_s[lc], s1 = as_s[lc + 1];
            float d0v = ad_s[lc], d1v = ad_s[lc + 1];
            pa0 = fmaf(acc[mt][nt][0], s0, fmaf(acc[mt][nt][1], s1, pa0));
            pd0 = fmaf(acc[mt][nt][0], d0v, fmaf(acc[mt][nt][1], d1v, pd0));
            pa8 = fmaf(acc[mt][nt][2], s0, fmaf(acc[mt][nt][3], s1, pa8));
            pd8 = fmaf(acc[mt][nt][2], d0v, fmaf(acc[mt][nt][3], d1v, pd8));
            if (r0 < NN)
                *(__half2*)&g_hh[(size_t)r0 * HC + bn + lc] =
                    __floats2half2_rn(acc[mt][nt][0], acc[mt][nt][1]);
            if (r0 + 8 < NN)
                *(__half2*)&g_hh[(size_t)(r0 + 8) * HC + bn + lc] =
                    __floats2half2_rn(acc[mt][nt][2], acc[mt][nt][3]);
        }
#pragma unroll
        for (int off = 1; off < 4; off <<= 1) {
            pa0 += __shfl_xor_sync(0xffffffffu, pa0, off);
            pd0 += __shfl_xor_sync(0xffffffffu, pd0, off);
            pa8 += __shfl_xor_sync(0xffffffffu, pa8, off);
            pd8 += __shfl_xor_sync(0xffffffffu, pd8, off);
        }
        if ((lane & 3) == 0) {
            int rl = mt * 16 + g;
            part_as[warp][rl]     = pa0;
            part_as[warp][rl + 8] = pa8;
            part_ad[warp][rl]     = pd0;
            part_ad[warp][rl + 8] = pd8;
        }
    }
    __syncthreads();
    {
        int r  = t & 127;            // local row
        int hl = t >> 7;             // local head 0/1
        int p  = (r >= 64) ? 1 : 0;
        int rl = r & 63;
        int w0 = p + hl * 4, w1 = p + 2 + hl * 4;
        if (bm + r < NN) {
            int hg = (bn >> 6) + hl;     // global head
            g_as[(bm + r) * 4 + hg] = part_as[w0][rl] + part_as[w1][rl];
            g_ad[(bm + r) * 4 + hg] = part_ad[w0][rl] + part_ad[w1][rl];
        }
    }
}

// ---------------- aggregation ----------------
__device__ __forceinline__ void fma8(float* acc, float wl, uint4 u) {
    union { uint4 uu; __half2 h[4]; } H; H.uu = u;
    float2 f0 = __half22float2(H.h[0]);
    float2 f1 = __half22float2(H.h[1]);
    float2 f2 = __half22float2(H.h[2]);
    float2 f3 = __half22float2(H.h[3]);
    acc[0] = fmaf(wl, f0.x, acc[0]); acc[1] = fmaf(wl, f0.y, acc[1]);
    acc[2] = fmaf(wl, f1.x, acc[2]); acc[3] = fmaf(wl, f1.y, acc[3]);
    acc[4] = fmaf(wl, f2.x, acc[4]); acc[5] = fmaf(wl, f2.y, acc[5]);
    acc[6] = fmaf(wl, f3.x, acc[6]); acc[7] = fmaf(wl, f3.y, acc[7]);
}

// TO_OUT=false: layer 1 -> ELU, write split bf16 directly into g_Ahi/g_Alo (KF=64 rows).
// TO_OUT=true : layer 2 -> write harness output.
template <bool TO_OUT>
__global__ void k_aggregate(const float* __restrict__ bias, float* __restrict__ out) {
    int warp = (blockIdx.x * blockDim.x + threadIdx.x) >> 5;
    if (warp >= NN) return;
    const int n = warp;
    const int l = threadIdx.x & 31;
    const int beg = g_rowptr[n];
    const int dr  = g_rowptr[n + 1] - beg;       // real edges; self handled logically
    const float4 adn = *(const float4*)&g_ad[n * 4];
    const float4 asn = *(const float4*)&g_as[n * 4];

    float4 ws;   // self-loop weight (logits O(1) bounded; no max-shift needed)
    ws.x = __expf(lrelu(asn.x + adn.x)); ws.y = __expf(lrelu(asn.y + adn.y));
    ws.z = __expf(lrelu(asn.z + adn.z)); ws.w = __expf(lrelu(asn.w + adn.w));

    float d0 = 0.f, d1 = 0.f, d2 = 0.f, d3 = 0.f;
    for (int i = l; i < dr; i += 32) {
        int s = g_csr[beg + i];
        float4 av = *(const float4*)&g_as[s * 4];
        float4 w;
        w.x = __expf(lrelu(av.x + adn.x)); w.y = __expf(lrelu(av.y + adn.y));
        w.z = __expf(lrelu(av.z + adn.z)); w.w = __expf(lrelu(av.w + adn.w));
        g_w4[beg + i] = w;
        d0 += w.x; d1 += w.y; d2 += w.z; d3 += w.w;
    }
#pragma unroll
    for (int off = 16; off; off >>= 1) {
        d0 += __shfl_xor_sync(0xffffffffu, d0, off);
        d1 += __shfl_xor_sync(0xffffffffu, d1, off);
        d2 += __shfl_xor_sync(0xffffffffu, d2, off);
        d3 += __shfl_xor_sync(0xffffffffu, d3, off);
    }
    d0 += ws.x; d1 += ws.y; d2 += ws.z; d3 += ws.w;
    const float r0 = 1.f / (d0 + 1e-16f), r1 = 1.f / (d1 + 1e-16f);
    const float r2 = 1.f / (d2 + 1e-16f), r3 = 1.f / (d3 + 1e-16f);
    __syncwarp();

    // pass C: fp16 weighted gather, unrolled x4 for MLP.
    const int hd = l >> 3;
    const float rh = (hd == 0) ? r0 : (hd == 1) ? r1 : (hd == 2) ? r2 : r3;
    const int c8 = 8 * l;
    float acc[8];
#pragma unroll
    for (int j = 0; j < 8; j++) acc[j] = 0.f;

    int i = 0;
    for (; i + 4 <= dr; i += 4) {
        int s0 = g_csr[beg + i + 0], s1 = g_csr[beg + i + 1];
        int s2 = g_csr[beg + i + 2], s3 = g_csr[beg + i + 3];
        float4 w0 = g_w4[beg + i + 0], w1 = g_w4[beg + i + 1];
        float4 w2 = g_w4[beg + i + 2], w3 = g_w4[beg + i + 3];
        uint4 u0 = *(const uint4*)&g_hh[(size_t)s0 * HC + c8];
        uint4 u1 = *(const uint4*)&g_hh[(size_t)s1 * HC + c8];
        uint4 u2 = *(const uint4*)&g_hh[(size_t)s2 * HC + c8];
        uint4 u3 = *(const uint4*)&g_hh[(size_t)s3 * HC + c8];
        float wl0 = ((hd == 0) ? w0.x : (hd == 1) ? w0.y : (hd == 2) ? w0.z : w0.w) * rh;
        float wl1 = ((hd == 0) ? w1.x : (hd == 1) ? w1.y : (hd == 2) ? w1.z : w1.w) * rh;
        float wl2 = ((hd == 0) ? w2.x : (hd == 1) ? w2.y : (hd == 2) ? w2.z : w2.w) * rh;
        float wl3 = ((hd == 0) ? w3.x : (hd == 1) ? w3.y : (hd == 2) ? w3.z : w3.w) * rh;
        fma8(acc, wl0, u0); fma8(acc, wl1, u1);
        fma8(acc, wl2, u2); fma8(acc, wl3, u3);
    }
    for (; i < dr; i++) {
        int s = g_csr[beg + i];
        float4 w = g_w4[beg + i];
        uint4 u = *(const uint4*)&g_hh[(size_t)s * HC + c8];
        float wl = ((hd == 0) ? w.x : (hd == 1) ? w.y : (hd == 2) ? w.z : w.w) * rh;
        fma8(acc, wl, u);
    }
    {   // self loop
        float wl = ((hd == 0) ? ws.x : (hd == 1) ? ws.y : (hd == 2) ? ws.z : ws.w) * rh;
        uint4 u = *(const uint4*)&g_hh[(size_t)n * HC + c8];
        fma8(acc, wl, u);
    }
#pragma unroll
    for (int j = 0; j < 8; j++) {
        acc[j] += __shfl_xor_sync(0xffffffffu, acc[j], 8);
        acc[j] += __shfl_xor_sync(0xffffffffu, acc[j], 16);
    }
    if (l < 8) {
        const float4 ba = *(const float4*)&bias[8 * l];
        const float4 bb = *(const float4*)&bias[8 * l + 4];
        float o[8];
#pragma unroll
        for (int j = 0; j < 8; j++) o[j] = acc[j] * 0.25f;
        o[0] += ba.x; o[1] += ba.y; o[2] += ba.z; o[3] += ba.w;
        o[4] += bb.x; o[5] += bb.y; o[6] += bb.z; o[7] += bb.w;
        if (!TO_OUT) {
            // ELU + split-bf16 store straight into layer-2's A operand
            union { __nv_bfloat16 b[8]; uint4 u; } Hh, Hl;
#pragma unroll
            for (int j = 0; j < 8; j++) {
                float v = o[j] > 0.f ? o[j] : expm1f(o[j]);
                __nv_bfloat16 hb = __float2bfloat16_rn(v);
                Hh.b[j] = hb;
                Hl.b[j] = __float2bfloat16_rn(v - __bfloat162float(hb));
            }
            *(uint4*)&g_Ahi[(size_t)n * HF + 8 * l] = Hh.u;
            *(uint4*)&g_Alo[(size_t)n * HF + 8 * l] = Hl.u;
        } else {
            *(float4*)&out[(size_t)n * HF + 8 * l]     = make_float4(o[0], o[1], o[2], o[3]);
            *(float4*)&out[(size_t)n * HF + 8 * l + 4] = make_float4(o[4], o[5], o[6], o[7]);
        }
    }
}

// ---------------- host launcher ----------------
extern "C" void kernel_launch(void* const* d_in, const int* in_sizes, int n_in,
                              void* d_out, int out_size) {
    const float* x   = (const float*)d_in[0];
    const void*  ei  = d_in[1];
    const float* W1  = (const float*)d_in[2];
    const float* as1 = (const float*)d_in[3];
    const float* ad1 = (const float*)d_in[4];
    const float* b1  = (const float*)d_in[5];
    const float* W2  = (const float*)d_in[6];
    const float* as2 = (const float*)d_in[7];
    const float* ad2 = (const float*)d_in[8];
    const float* b2  = (const float*)d_in[9];
    float*       out = (float*)d_out;

    const int warps_grid = (NN * 32 + 255) / 256;

    k_prep<<<NBLK, 256>>>((const long long*)ei, W1, W2);          // deg=0, probe, W1/W2 cvt
    k_hist_cvt<<<HIST_BLOCKS + XCVT_BLOCKS, 256>>>(ei, x);        // hist + x cvt concurrent
    k_partial<<<NBLK, 256>>>();
    k_scanb<<<1, 256>>>();
    k_write<<<NBLK, 256>>>();

    // layer 1: GEMM + alpha epilogue, with CSR scatter fused in (concurrent blocks)
    k_mma<IN_F, 1, true><<<GEMM_BLOCKS + HIST_BLOCKS, 256>>>(as1, ad1, ei);
    k_aggregate<false><<<warps_grid, 256>>>(b1, nullptr);         // writes split-bf16 A

    // layer 2
    k_mma<HF, 2, false><<<GEMM_BLOCKS, 256>>>(as2, ad2, ei);
    k_aggregate<true><<<warps_grid, 256>>>(b2, out);
}

// round 14
// speedup vs baseline: 1.6532x; 1.0013x over previous
#include <cuda_runtime.h>
#include <cuda_bf16.h>
#include <cuda_fp16.h>
#include <cstdint>

#define NN 50000
#define EE 800000
#define IN_F 128
#define HF 64
#define HEADS 4
#define HC 256            // HEADS*HF
#define NEG_SLOPE 0.2f
#define NBLK ((NN + 255) / 256)         // 196
#define HIST_BLOCKS ((EE + 255) / 256)  // 3125
#define XCVT_BLOCKS ((NN * IN_F / 4 + 255) / 256)  // 6250
#define GEMM_BLOCKS (((NN + 127) / 128) * 2)       // 782

// ---------------- device scratch ----------------
__device__ __align__(16) __half g_hh[(size_t)NN * HC];    // fp16 features for gather
__device__ __align__(16) float g_as[NN * HEADS];
__device__ __align__(16) float g_ad[NN * HEADS];
__device__ __align__(16) float4 g_w4[EE];                 // per-edge softmax weights
__device__ __align__(16) __nv_bfloat16 g_Ahi[(size_t)NN * IN_F];
__device__ __align__(16) __nv_bfloat16 g_Alo[(size_t)NN * IN_F];
__device__ __align__(16) __nv_bfloat16 g_B1hi[HC * IN_F];
__device__ __align__(16) __nv_bfloat16 g_B1lo[HC * IN_F];
__device__ __align__(16) __nv_bfloat16 g_B2hi[HC * HF];
__device__ __align__(16) __nv_bfloat16 g_B2lo[HC * HF];
__device__ int   g_deg[NN];              // static zero; re-zeroed by k_scan1 each launch
__device__ int   g_rowptr[NN + 1];
__device__ int   g_cursor[NN];
__device__ int   g_csr[EE];
__device__ unsigned long long g_look[NBLK];  // lookback descriptors; cleared by k_prep
__device__ int   g_is64 = 1;             // probes only ever write 0 (deterministic)

__device__ __forceinline__ float lrelu(float v) { return v > 0.f ? v : NEG_SLOPE * v; }

// convert one float4 (4 values) into split bf16 at element index 4*i
__device__ __forceinline__ void cvt4(float4 v, __nv_bfloat16* hi, __nv_bfloat16* lo, int i) {
    __nv_bfloat16 hx = __float2bfloat16_rn(v.x);
    __nv_bfloat16 hy = __float2bfloat16_rn(v.y);
    __nv_bfloat16 hz = __float2bfloat16_rn(v.z);
    __nv_bfloat16 hw = __float2bfloat16_rn(v.w);
    __nv_bfloat16 lx = __float2bfloat16_rn(v.x - __bfloat162float(hx));
    __nv_bfloat16 ly = __float2bfloat16_rn(v.y - __bfloat162float(hy));
    __nv_bfloat16 lz = __float2bfloat16_rn(v.z - __bfloat162float(hz));
    __nv_bfloat16 lw = __float2bfloat16_rn(v.w - __bfloat162float(hw));
    ((__nv_bfloat162*)hi)[2 * i]     = __halves2bfloat162(hx, hy);
    ((__nv_bfloat162*)hi)[2 * i + 1] = __halves2bfloat162(hz, hw);
    ((__nv_bfloat162*)lo)[2 * i]     = __halves2bfloat162(lx, ly);
    ((__nv_bfloat162*)lo)[2 * i + 1] = __halves2bfloat162(lz, lw);
}

// ---------------- prep: dtype probe + W1/W2 cvt + lookback-flag clear ----------
__global__ void k_prep(const long long* __restrict__ ei,
                       const float* __restrict__ W1, const float* __restrict__ W2) {
    int i = blockIdx.x * blockDim.x + threadIdx.x;
    if (i < 4096) {                       // sampled dtype probe
        long long v = ei[(size_t)i * 195];
        if (v < 0 || v >= NN) g_is64 = 0;
    }
    if (i < NBLK) g_look[i] = 0ULL;       // reset lookback state for this launch
    if (i < HC * IN_F / 4) cvt4(((const float4*)W1)[i], g_B1hi, g_B1lo, i);
    if (i < HC * HF / 4)   cvt4(((const float4*)W2)[i], g_B2hi, g_B2lo, i);
}

// histogram (blocks [0,HIST_BLOCKS)) + x -> split bf16 (remaining blocks)
__global__ void k_hist_cvt(const void* __restrict__ eiv, const float* __restrict__ x) {
    if (blockIdx.x < HIST_BLOCKS) {
        int e = blockIdx.x * 256 + threadIdx.x;
        if (e < EE) {
            int d = g_is64 ? (int)((const long long*)eiv)[EE + e]
                           : ((const int*)eiv)[EE + e];
            if ((unsigned)d < NN) atomicAdd(&g_deg[d], 1);
        }
    } else {
        int i = (blockIdx.x - HIST_BLOCKS) * 256 + threadIdx.x;
        if (i < NN * IN_F / 4) cvt4(((const float4*)x)[i], g_Ahi, g_Alo, i);
    }
}

// ---------------- single-pass decoupled-lookback scan ----------------
// g_deg -> exclusive prefix in g_rowptr/g_cursor; also re-zeroes g_deg.
// All 196 CTAs are co-resident (196 << chip capacity) so spinning is safe.
__global__ void __launch_bounds__(256) k_scan1() {
    __shared__ int sm[256];
    __shared__ int s_pfx;
    const int b = blockIdx.x, t = threadIdx.x;
    const int i = b * 256 + t;
    int v = (i < NN) ? g_deg[i] : 0;
    if (i < NN) g_deg[i] = 0;            // re-zero for next graph replay
    sm[t] = v;
    __syncthreads();
#pragma unroll
    for (int off = 1; off < 256; off <<= 1) {
        int x = (t >= off) ? sm[t - off] : 0;
        __syncthreads();
        sm[t] += x;
        __syncthreads();
    }
    const int total = sm[255];

    if (b == 0) {
        if (t == 0) {
            s_pfx = 0;
            atomicExch(&g_look[0], (2ULL << 32) | (unsigned)total);  // inclusive prefix
        }
    } else {
        if (t == 0)
            atomicExch(&g_look[b], (1ULL << 32) | (unsigned)total);  // aggregate
        if (t < 32) {                                   // warp-parallel lookback
            int pfx = 0;
            int base = b - 1;
            while (true) {
                int j = base - t;
                unsigned long long d = (j >= 0)
                    ? atomicAdd(&g_look[j], 0ULL)       // atomic read (L2-coherent)
                    : (2ULL << 32);                     // virtual terminator, value 0
                unsigned f = (unsigned)(d >> 32);
                unsigned bal2 = __ballot_sync(0xffffffffu, f == 2);
                unsigned bal0 = __ballot_sync(0xffffffffu, f == 0);
                if (bal0 == 0) {
                    if (bal2) {                         // nearest flag-2 at lane L
                        int L = __ffs(bal2) - 1;
                        int val = (t <= L) ? (int)(unsigned)d : 0;
#pragma unroll
                        for (int o = 16; o; o >>= 1) val += __shfl_xor_sync(0xffffffffu, val, o);
                        pfx += val;
                        break;
                    } else {                            // whole window is aggregates
                        int val = (int)(unsigned)d;
#pragma unroll
                        for (int o = 16; o; o >>= 1) val += __shfl_xor_sync(0xffffffffu, val, o);
                        pfx += val;
                        base -= 32;
                    }
                }
            }
            if (t == 0) {
                s_pfx = pfx;
                atomicExch(&g_look[b], (2ULL << 32) | (unsigned)(total + pfx));
            }
        }
    }
    __syncthreads();
    const int pfx = s_pfx;
    if (i < NN) {
        int excl = pfx + sm[t] - v;
        g_rowptr[i] = excl;
        g_cursor[i] = excl;
    }
    if (i == NN - 1) g_rowptr[NN] = pfx + sm[t];
}

// ---------------- tensor-core GEMM + fused alpha/fp16 epilogue ----------------
__device__ __forceinline__ void mma16816(float* c, const uint32_t* a, uint32_t b0, uint32_t b1) {
    asm volatile(
        "mma.sync.aligned.m16n8k16.row.col.f32.bf16.bf16.f32 "
        "{%0,%1,%2,%3},{%4,%5,%6,%7},{%8,%9},{%0,%1,%2,%3};"
        : "+f"(c[0]), "+f"(c[1]), "+f"(c[2]), "+f"(c[3])
        : "r"(a[0]), "r"(a[1]), "r"(a[2]), "r"(a[3]), "r"(b0), "r"(b1));
}

template <int KF, int LAYER, bool FUSE_SCATTER>
__global__ void __launch_bounds__(256) k_mma(const float* __restrict__ a_src,
                                             const float* __restrict__ a_dst,
                                             const void* __restrict__ eiv) {
    __shared__ __align__(16) __nv_bfloat16 Ah[128][40], Al[128][40];
    __shared__ __align__(16) __nv_bfloat16 Bh[128][40], Bl[128][40];
    __shared__ float as_s[128], ad_s[128];
    __shared__ float part_as[8][64], part_ad[8][64];

    if (FUSE_SCATTER && blockIdx.x >= GEMM_BLOCKS) {     // concurrent CSR scatter
        int e = (blockIdx.x - GEMM_BLOCKS) * 256 + threadIdx.x;
        if (e < EE) {
            int s, d;
            if (g_is64) {
                s = (int)((const long long*)eiv)[e];
                d = (int)((const long long*)eiv)[EE + e];
            } else {
                s = ((const int*)eiv)[e];
                d = ((const int*)eiv)[EE + e];
            }
            if ((unsigned)s < NN && (unsigned)d < NN) {
                int p = atomicAdd(&g_cursor[d], 1);
                g_csr[p] = s;
            }
        }
        return;
    }

    const __nv_bfloat16* Bhi = (LAYER == 1) ? g_B1hi : g_B2hi;
    const __nv_bfloat16* Blo = (LAYER == 1) ? g_B1lo : g_B2lo;
    const int t = threadIdx.x;
    const int bm = (blockIdx.x >> 1) * 128, bn = (blockIdx.x & 1) * 128;
    const int warp = t >> 5, lane = t & 31;
    const int wr = (warp & 1) * 64, wc = (warp >> 1) * 32;
    const int g = lane >> 2, tg = (lane & 3) * 2;

    if (t < 128) {
        as_s[t] = a_src[bn + t];
        ad_s[t] = a_dst[bn + t];
    }

    float acc[4][4][4];
#pragma unroll
    for (int a = 0; a < 4; a++)
#pragma unroll
        for (int b = 0; b < 4; b++)
#pragma unroll
            for (int c = 0; c < 4; c++) acc[a][b][c] = 0.f;

    for (int k0 = 0; k0 < KF; k0 += 32) {
#pragma unroll
        for (int u = t; u < 512; u += 256) {
            int r = u >> 2, cg = (u & 3) * 8;
            uint4 vh = make_uint4(0, 0, 0, 0), vl = vh;
            int gm = bm + r;
            if (gm < NN) {
                vh = *(const uint4*)&g_Ahi[(size_t)gm * KF + k0 + cg];
                vl = *(const uint4*)&g_Alo[(size_t)gm * KF + k0 + cg];
            }
            *(uint4*)&Ah[r][cg] = vh;
            *(uint4*)&Al[r][cg] = vl;
            *(uint4*)&Bh[r][cg] = *(const uint4*)&Bhi[(size_t)(bn + r) * KF + k0 + cg];
            *(uint4*)&Bl[r][cg] = *(const uint4*)&Blo[(size_t)(bn + r) * KF + k0 + cg];
        }
        __syncthreads();
#pragma unroll
        for (int kk = 0; kk < 32; kk += 16) {
            uint32_t ah[4][4], al[4][4];
#pragma unroll
            for (int mt = 0; mt < 4; mt++) {
                int r0 = wr + mt * 16 + g;
                ah[mt][0] = *(const uint32_t*)&Ah[r0][kk + tg];
                ah[mt][1] = *(const uint32_t*)&Ah[r0 + 8][kk + tg];
                ah[mt][2] = *(const uint32_t*)&Ah[r0][kk + tg + 8];
                ah[mt][3] = *(const uint32_t*)&Ah[r0 + 8][kk + tg + 8];
                al[mt][0] = *(const uint32_t*)&Al[r0][kk + tg];
                al[mt][1] = *(const uint32_t*)&Al[r0 + 8][kk + tg];
                al[mt][2] = *(const uint32_t*)&Al[r0][kk + tg + 8];
                al[mt][3] = *(const uint32_t*)&Al[r0 + 8][kk + tg + 8];
            }
#pragma unroll
            for (int nt = 0; nt < 4; nt++) {
                int c0 = wc + nt * 8 + g;
                uint32_t bh0 = *(const uint32_t*)&Bh[c0][kk + tg];
                uint32_t bh1 = *(const uint32_t*)&Bh[c0][kk + tg + 8];
                uint32_t bl0 = *(const uint32_t*)&Bl[c0][kk + tg];
                uint32_t bl1 = *(const uint32_t*)&Bl[c0][kk + tg + 8];
#pragma unroll
                for (int mt = 0; mt < 4; mt++) {
                    mma16816(acc[mt][nt], ah[mt], bh0, bh1);
                    mma16816(acc[mt][nt], ah[mt], bl0, bl1);
                    mma16816(acc[mt][nt], al[mt], bh0, bh1);
                }
            }
        }
        __syncthreads();
    }

    // ---- epilogue: fp16 store + per-row alpha partials ----
#pragma unroll
    for (int mt = 0; mt < 4; mt++) {
        int r0 = bm + wr + mt * 16 + g;
        float pa0 = 0.f, pd0 = 0.f, pa8 = 0.f, pd8 = 0.f;
#pragma unroll
        for (int nt = 0; nt < 4; nt++) {
            int lc = wc + nt * 8 + tg;
            float s0 = as_s[lc], s1 = as_s[lc + 1];
            float d0v = ad_s[lc], d1v = ad_s[lc + 1];
            pa0 = fmaf(acc[mt][nt][0], s0, fmaf(acc[mt][nt][1], s1, pa0));
            pd0 = fmaf(acc[mt][nt][0], d0v, fmaf(acc[mt][nt][1], d1v, pd0));
            pa8 = fmaf(acc[mt][nt][2], s0, fmaf(acc[mt][nt][3], s1, pa8));
            pd8 = fmaf(acc[mt][nt][2], d0v, fmaf(acc[mt][nt][3], d1v, pd8));
            if (r0 < NN)
                *(__half2*)&g_hh[(size_t)r0 * HC + bn + lc] =
                    __floats2half2_rn(acc[mt][nt][0], acc[mt][nt][1]);
            if (r0 + 8 < NN)
                *(__half2*)&g_hh[(size_t)(r0 + 8) * HC + bn + lc] =
                    __floats2half2_rn(acc[mt][nt][2], acc[mt][nt][3]);
        }
#pragma unroll
        for (int off = 1; off < 4; off <<= 1) {
            pa0 += __shfl_xor_sync(0xffffffffu, pa0, off);
            pd0 += __shfl_xor_sync(0xffffffffu, pd0, off);
            pa8 += __shfl_xor_sync(0xffffffffu, pa8, off);
            pd8 += __shfl_xor_sync(0xffffffffu, pd8, off);
        }
        if ((lane & 3) == 0) {
            int rl = mt * 16 + g;
            part_as[warp][rl]     = pa0;
            part_as[warp][rl + 8] = pa8;
            part_ad[warp][rl]     = pd0;
            part_ad[warp][rl + 8] = pd8;
        }
    }
    __syncthreads();
    {
        int r  = t & 127;            // local row
        int hl = t >> 7;             // local head 0/1
        int p  = (r >= 64) ? 1 : 0;
        int rl = r & 63;
        int w0 = p + hl * 4, w1 = p + 2 + hl * 4;
        if (bm + r < NN) {
            int hg = (bn >> 6) + hl;     // global head
            g_as[(bm + r) * 4 + hg] = part_as[w0][rl] + part_as[w1][rl];
            g_ad[(bm + r) * 4 + hg] = part_ad[w0][rl] + part_ad[w1][rl];
        }
    }
}

// ---------------- aggregation ----------------
__device__ __forceinline__ void fma8(float* acc, float wl, uint4 u) {
    union { uint4 uu; __half2 h[4]; } H; H.uu = u;
    float2 f0 = __half22float2(H.h[0]);
    float2 f1 = __half22float2(H.h[1]);
    float2 f2 = __half22float2(H.h[2]);
    float2 f3 = __half22float2(H.h[3]);
    acc[0] = fmaf(wl, f0.x, acc[0]); acc[1] = fmaf(wl, f0.y, acc[1]);
    acc[2] = fmaf(wl, f1.x, acc[2]); acc[3] = fmaf(wl, f1.y, acc[3]);
    acc[4] = fmaf(wl, f2.x, acc[4]); acc[5] = fmaf(wl, f2.y, acc[5]);
    acc[6] = fmaf(wl, f3.x, acc[6]); acc[7] = fmaf(wl, f3.y, acc[7]);
}

// TO_OUT=false: layer 1 -> ELU, write split bf16 into g_Ahi/g_Alo (HF cols).
// TO_OUT=true : layer 2 -> write harness output.
template <bool TO_OUT>
__global__ void k_aggregate(const float* __restrict__ bias, float* __restrict__ out) {
    int warp = (blockIdx.x * blockDim.x + threadIdx.x) >> 5;
    if (warp >= NN) return;
    const int n = warp;
    const int l = threadIdx.x & 31;
    const int beg = g_rowptr[n];
    const int dr  = g_rowptr[n + 1] - beg;       // real edges; self handled logically
    const float4 adn = *(const float4*)&g_ad[n * 4];
    const float4 asn = *(const float4*)&g_as[n * 4];

    float4 ws;   // self-loop weight (logits O(1) bounded; no max-shift needed)
    ws.x = __expf(lrelu(asn.x + adn.x)); ws.y = __expf(lrelu(asn.y + adn.y));
    ws.z = __expf(lrelu(asn.z + adn.z)); ws.w = __expf(lrelu(asn.w + adn.w));

    float d0 = 0.f, d1 = 0.f, d2 = 0.f, d3 = 0.f;
    for (int i = l; i < dr; i += 32) {
        int s = g_csr[beg + i];
        float4 av = *(const float4*)&g_as[s * 4];
        float4 w;
        w.x = __expf(lrelu(av.x + adn.x)); w.y = __expf(lrelu(av.y + adn.y));
        w.z = __expf(lrelu(av.z + adn.z)); w.w = __expf(lrelu(av.w + adn.w));
        g_w4[beg + i] = w;
        d0 += w.x; d1 += w.y; d2 += w.z; d3 += w.w;
    }
#pragma unroll
    for (int off = 16; off; off >>= 1) {
        d0 += __shfl_xor_sync(0xffffffffu, d0, off);
        d1 += __shfl_xor_sync(0xffffffffu, d1, off);
        d2 += __shfl_xor_sync(0xffffffffu, d2, off);
        d3 += __shfl_xor_sync(0xffffffffu, d3, off);
    }
    d0 += ws.x; d1 += ws.y; d2 += ws.z; d3 += ws.w;
    const float r0 = 1.f / (d0 + 1e-16f), r1 = 1.f / (d1 + 1e-16f);
    const float r2 = 1.f / (d2 + 1e-16f), r3 = 1.f / (d3 + 1e-16f);
    __syncwarp();

    // pass C: fp16 weighted gather, unrolled x4 for MLP.
    const int hd = l >> 3;
    const float rh = (hd == 0) ? r0 : (hd == 1) ? r1 : (hd == 2) ? r2 : r3;
    const int c8 = 8 * l;
    float acc[8];
#pragma unroll
    for (int j = 0; j < 8; j++) acc[j] = 0.f;

    int i = 0;
    for (; i + 4 <= dr; i += 4) {
        int s0 = g_csr[beg + i + 0], s1 = g_csr[beg + i + 1];
        int s2 = g_csr[beg + i + 2], s3 = g_csr[beg + i + 3];
        float4 w0 = g_w4[beg + i + 0], w1 = g_w4[beg + i + 1];
        float4 w2 = g_w4[beg + i + 2], w3 = g_w4[beg + i + 3];
        uint4 u0 = *(const uint4*)&g_hh[(size_t)s0 * HC + c8];
        uint4 u1 = *(const uint4*)&g_hh[(size_t)s1 * HC + c8];
        uint4 u2 = *(const uint4*)&g_hh[(size_t)s2 * HC + c8];
        uint4 u3 = *(const uint4*)&g_hh[(size_t)s3 * HC + c8];
        float wl0 = ((hd == 0) ? w0.x : (hd == 1) ? w0.y : (hd == 2) ? w0.z : w0.w) * rh;
        float wl1 = ((hd == 0) ? w1.x : (hd == 1) ? w1.y : (hd == 2) ? w1.z : w1.w) * rh;
        float wl2 = ((hd == 0) ? w2.x : (hd == 1) ? w2.y : (hd == 2) ? w2.z : w2.w) * rh;
        float wl3 = ((hd == 0) ? w3.x : (hd == 1) ? w3.y : (hd == 2) ? w3.z : w3.w) * rh;
        fma8(acc, wl0, u0); fma8(acc, wl1, u1);
        fma8(acc, wl2, u2); fma8(acc, wl3, u3);
    }
    for (; i < dr; i++) {
        int s = g_csr[beg + i];
        float4 w = g_w4[beg + i];
        uint4 u = *(const uint4*)&g_hh[(size_t)s * HC + c8];
        float wl = ((hd == 0) ? w.x : (hd == 1) ? w.y : (hd == 2) ? w.z : w.w) * rh;
        fma8(acc, wl, u);
    }
    {   // self loop
        float wl = ((hd == 0) ? ws.x : (hd == 1) ? ws.y : (hd == 2) ? ws.z : ws.w) * rh;
        uint4 u = *(const uint4*)&g_hh[(size_t)n * HC + c8];
        fma8(acc, wl, u);
    }
#pragma unroll
    for (int j = 0; j < 8; j++) {
        acc[j] += __shfl_xor_sync(0xffffffffu, acc[j], 8);
        acc[j] += __shfl_xor_sync(0xffffffffu, acc[j], 16);
    }
    if (l < 8) {
        const float4 ba = *(const float4*)&bias[8 * l];
        const float4 bb = *(const float4*)&bias[8 * l + 4];
        float o[8];
#pragma unroll
        for (int j = 0; j < 8; j++) o[j] = acc[j] * 0.25f;
        o[0] += ba.x; o[1] += ba.y; o[2] += ba.z; o[3] += ba.w;
        o[4] += bb.x; o[5] += bb.y; o[6] += bb.z; o[7] += bb.w;
        if (!TO_OUT) {
            // ELU + split-bf16 store straight into layer-2's A operand
            union { __nv_bfloat16 b[8]; uint4 u; } Hh, Hl;
#pragma unroll
            for (int j = 0; j < 8; j++) {
                float v = o[j] > 0.f ? o[j] : expm1f(o[j]);
                __nv_bfloat16 hb = __float2bfloat16_rn(v);
                Hh.b[j] = hb;
                Hl.b[j] = __float2bfloat16_rn(v - __bfloat162float(hb));
            }
            *(uint4*)&g_Ahi[(size_t)n * HF + 8 * l] = Hh.u;
            *(uint4*)&g_Alo[(size_t)n * HF + 8 * l] = Hl.u;
        } else {
            *(float4*)&out[(size_t)n * HF + 8 * l]     = make_float4(o[0], o[1], o[2], o[3]);
            *(float4*)&out[(size_t)n * HF + 8 * l + 4] = make_float4(o[4], o[5], o[6], o[7]);
        }
    }
}

// ---------------- host launcher ----------------
extern "C" void kernel_launch(void* const* d_in, const int* in_sizes, int n_in,
                              void* d_out, int out_size) {
    const float* x   = (const float*)d_in[0];
    const void*  ei  = d_in[1];
    const float* W1  = (const float*)d_in[2];
    const float* as1 = (const float*)d_in[3];
    const float* ad1 = (const float*)d_in[4];
    const float* b1  = (const float*)d_in[5];
    const float* W2  = (const float*)d_in[6];
    const float* as2 = (const float*)d_in[7];
    const float* ad2 = (const float*)d_in[8];
    const float* b2  = (const float*)d_in[9];
    float*       out = (float*)d_out;

    const int warps_grid = (NN * 32 + 255) / 256;

    k_prep<<<64, 256>>>((const long long*)ei, W1, W2);            // probe, W cvt, flag clear
    k_hist_cvt<<<HIST_BLOCKS + XCVT_BLOCKS, 256>>>(ei, x);        // hist + x cvt concurrent
    k_scan1<<<NBLK, 256>>>();                                     // single-pass lookback scan

    // layer 1: GEMM + alpha epilogue, with CSR scatter fused in (concurrent blocks)
    k_mma<IN_F, 1, true><<<GEMM_BLOCKS + HIST_BLOCKS, 256>>>(as1, ad1, ei);
    k_aggregate<false><<<warps_grid, 256>>>(b1, nullptr);         // writes split-bf16 A

    // layer 2
    k_mma<HF, 2, false><<<GEMM_BLOCKS, 256>>>(as2, ad2, ei);
    k_aggregate<true><<<warps_grid, 256>>>(b2, out);
}

// round 15
// speedup vs baseline: 1.7125x; 1.0359x over previous
#include <cuda_runtime.h>
#include <cuda_bf16.h>
#include <cuda_fp16.h>
#include <cstdint>

#define NN 50000
#define EE 800000
#define IN_F 128
#define HF 64
#define HEADS 4
#define HC 256            // HEADS*HF
#define NEG_SLOPE 0.2f
#define NBLK ((NN + 255) / 256)         // 196
#define HIST_BLOCKS ((EE + 255) / 256)  // 3125
#define XCVT_BLOCKS ((NN * IN_F / 4 + 255) / 256)  // 6250
#define GEMM_BLOCKS (((NN + 127) / 128) * 2)       // 782
#define SCATTER_BLOCKS 600

// ---------------- device scratch ----------------
__device__ __align__(16) __half g_hh[(size_t)NN * HC];    // fp16 features for gather
__device__ __align__(16) float g_as[NN * HEADS];
__device__ __align__(16) float g_ad[NN * HEADS];
__device__ __align__(16) float4 g_w4[EE];                 // per-edge softmax weights
__device__ __align__(16) __nv_bfloat16 g_Ahi[(size_t)NN * IN_F];
__device__ __align__(16) __nv_bfloat16 g_Alo[(size_t)NN * IN_F];
__device__ __align__(16) __nv_bfloat16 g_B1hi[HC * IN_F];
__device__ __align__(16) __nv_bfloat16 g_B1lo[HC * IN_F];
__device__ __align__(16) __nv_bfloat16 g_B2hi[HC * HF];
__device__ __align__(16) __nv_bfloat16 g_B2lo[HC * HF];
__device__ int   g_deg[NN];              // static zero; re-zeroed by k_scan1 each launch
__device__ int   g_rowptr[NN + 1];
__device__ int   g_cursor[NN];
__device__ int   g_csr[EE];
__device__ unsigned long long g_look[NBLK];  // lookback descriptors; cleared by k_prep
__device__ int   g_is64 = 1;             // probes only ever write 0 (deterministic)

__device__ __forceinline__ float lrelu(float v) { return v > 0.f ? v : NEG_SLOPE * v; }

// convert one float4 (4 values) into split bf16 at element index 4*i
__device__ __forceinline__ void cvt4(float4 v, __nv_bfloat16* hi, __nv_bfloat16* lo, int i) {
    __nv_bfloat16 hx = __float2bfloat16_rn(v.x);
    __nv_bfloat16 hy = __float2bfloat16_rn(v.y);
    __nv_bfloat16 hz = __float2bfloat16_rn(v.z);
    __nv_bfloat16 hw = __float2bfloat16_rn(v.w);
    __nv_bfloat16 lx = __float2bfloat16_rn(v.x - __bfloat162float(hx));
    __nv_bfloat16 ly = __float2bfloat16_rn(v.y - __bfloat162float(hy));
    __nv_bfloat16 lz = __float2bfloat16_rn(v.z - __bfloat162float(hz));
    __nv_bfloat16 lw = __float2bfloat16_rn(v.w - __bfloat162float(hw));
    ((__nv_bfloat162*)hi)[2 * i]     = __halves2bfloat162(hx, hy);
    ((__nv_bfloat162*)hi)[2 * i + 1] = __halves2bfloat162(hz, hw);
    ((__nv_bfloat162*)lo)[2 * i]     = __halves2bfloat162(lx, ly);
    ((__nv_bfloat162*)lo)[2 * i + 1] = __halves2bfloat162(lz, lw);
}

// ---------------- prep: dtype probe + W1/W2 cvt + lookback-flag clear ----------
__global__ void k_prep(const long long* __restrict__ ei,
                       const float* __restrict__ W1, const float* __restrict__ W2) {
    int i = blockIdx.x * blockDim.x + threadIdx.x;
    if (i < 4096) {                       // sampled dtype probe
        long long v = ei[(size_t)i * 195];
        if (v < 0 || v >= NN) g_is64 = 0;
    }
    if (i < NBLK) g_look[i] = 0ULL;       // reset lookback state for this launch
    if (i < HC * IN_F / 4) cvt4(((const float4*)W1)[i], g_B1hi, g_B1lo, i);
    if (i < HC * HF / 4)   cvt4(((const float4*)W2)[i], g_B2hi, g_B2lo, i);
}

// histogram (blocks [0,HIST_BLOCKS)) + x -> split bf16 (remaining blocks)
__global__ void k_hist_cvt(const void* __restrict__ eiv, const float* __restrict__ x) {
    if (blockIdx.x < HIST_BLOCKS) {
        int e = blockIdx.x * 256 + threadIdx.x;
        if (e < EE) {
            int d = g_is64 ? (int)((const long long*)eiv)[EE + e]
                           : ((const int*)eiv)[EE + e];
            if ((unsigned)d < NN) atomicAdd(&g_deg[d], 1);
        }
    } else {
        int i = (blockIdx.x - HIST_BLOCKS) * 256 + threadIdx.x;
        if (i < NN * IN_F / 4) cvt4(((const float4*)x)[i], g_Ahi, g_Alo, i);
    }
}

// ---------------- single-pass decoupled-lookback scan ----------------
__global__ void __launch_bounds__(256) k_scan1() {
    __shared__ int sm[256];
    __shared__ int s_pfx;
    const int b = blockIdx.x, t = threadIdx.x;
    const int i = b * 256 + t;
    int v = (i < NN) ? g_deg[i] : 0;
    if (i < NN) g_deg[i] = 0;            // re-zero for next graph replay
    sm[t] = v;
    __syncthreads();
#pragma unroll
    for (int off = 1; off < 256; off <<= 1) {
        int x = (t >= off) ? sm[t - off] : 0;
        __syncthreads();
        sm[t] += x;
        __syncthreads();
    }
    const int total = sm[255];

    if (b == 0) {
        if (t == 0) {
            s_pfx = 0;
            atomicExch(&g_look[0], (2ULL << 32) | (unsigned)total);
        }
    } else {
        if (t == 0)
            atomicExch(&g_look[b], (1ULL << 32) | (unsigned)total);
        if (t < 32) {                                   // warp-parallel lookback
            int pfx = 0;
            int base = b - 1;
            while (true) {
                int j = base - t;
                unsigned long long d = (j >= 0)
                    ? atomicAdd(&g_look[j], 0ULL)
                    : (2ULL << 32);
                unsigned f = (unsigned)(d >> 32);
                unsigned bal2 = __ballot_sync(0xffffffffu, f == 2);
                unsigned bal0 = __ballot_sync(0xffffffffu, f == 0);
                if (bal0 == 0) {
                    if (bal2) {
                        int L = __ffs(bal2) - 1;
                        int val = (t <= L) ? (int)(unsigned)d : 0;
#pragma unroll
                        for (int o = 16; o; o >>= 1) val += __shfl_xor_sync(0xffffffffu, val, o);
                        pfx += val;
                        break;
                    } else {
                        int val = (int)(unsigned)d;
#pragma unroll
                        for (int o = 16; o; o >>= 1) val += __shfl_xor_sync(0xffffffffu, val, o);
                        pfx += val;
                        base -= 32;
                    }
                }
            }
            if (t == 0) {
                s_pfx = pfx;
                atomicExch(&g_look[b], (2ULL << 32) | (unsigned)(total + pfx));
            }
        }
    }
    __syncthreads();
    const int pfx = s_pfx;
    if (i < NN) {
        int excl = pfx + sm[t] - v;
        g_rowptr[i] = excl;
        g_cursor[i] = excl;
    }
    if (i == NN - 1) g_rowptr[NN] = pfx + sm[t];
}

// ---------------- tensor-core GEMM + fused alpha/fp16 epilogue ----------------
__device__ __forceinline__ void mma16816(float* c, const uint32_t* a, uint32_t b0, uint32_t b1) {
    asm volatile(
        "mma.sync.aligned.m16n8k16.row.col.f32.bf16.bf16.f32 "
        "{%0,%1,%2,%3},{%4,%5,%6,%7},{%8,%9},{%0,%1,%2,%3};"
        : "+f"(c[0]), "+f"(c[1]), "+f"(c[2]), "+f"(c[3])
        : "r"(a[0]), "r"(a[1]), "r"(a[2]), "r"(a[3]), "r"(b0), "r"(b1));
}

__device__ __forceinline__ void ldsm_x4(uint32_t& r0, uint32_t& r1, uint32_t& r2, uint32_t& r3,
                                        uint32_t addr) {
    asm volatile("ldmatrix.sync.aligned.m8n8.x4.shared.b16 {%0,%1,%2,%3}, [%4];"
                 : "=r"(r0), "=r"(r1), "=r"(r2), "=r"(r3) : "r"(addr));
}

template <int KF, int LAYER, bool FUSE_SCATTER>
__global__ void __launch_bounds__(256) k_mma(const float* __restrict__ a_src,
                                             const float* __restrict__ a_dst,
                                             const void* __restrict__ eiv) {
    __shared__ __align__(16) __nv_bfloat16 Ah[128][40], Al[128][40];
    __shared__ __align__(16) __nv_bfloat16 Bh[128][40], Bl[128][40];
    __shared__ float as_s[128], ad_s[128];
    __shared__ float part_as[8][64], part_ad[8][64];

    if (FUSE_SCATTER && blockIdx.x >= GEMM_BLOCKS) {     // concurrent grid-stride scatter
        for (int e = (blockIdx.x - GEMM_BLOCKS) * 256 + threadIdx.x; e < EE;
             e += SCATTER_BLOCKS * 256) {
            int s, d;
            if (g_is64) {
                s = (int)((const long long*)eiv)[e];
                d = (int)((const long long*)eiv)[EE + e];
            } else {
                s = ((const int*)eiv)[e];
                d = ((const int*)eiv)[EE + e];
            }
            if ((unsigned)s < NN && (unsigned)d < NN) {
                int p = atomicAdd(&g_cursor[d], 1);
                g_csr[p] = s;
            }
        }
        return;
    }

    const __nv_bfloat16* Bhi = (LAYER == 1) ? g_B1hi : g_B2hi;
    const __nv_bfloat16* Blo = (LAYER == 1) ? g_B1lo : g_B2lo;
    const int t = threadIdx.x;
    const int bm = (blockIdx.x >> 1) * 128, bn = (blockIdx.x & 1) * 128;
    const int warp = t >> 5, lane = t & 31;
    const int wr = (warp & 1) * 64, wc = (warp >> 1) * 32;
    const int g = lane >> 2, tg = (lane & 3) * 2;

    if (t < 128) {
        as_s[t] = a_src[bn + t];
        ad_s[t] = a_dst[bn + t];
    }

    // ldmatrix per-lane addressing: row_off = lane&15, col_off = 8 if lane>=16
    const int rowo = lane & 15;
    const int col8 = (lane & 16) >> 1;
    const uint32_t sAh = (uint32_t)__cvta_generic_to_shared(&Ah[0][0]);
    const uint32_t sAl = (uint32_t)__cvta_generic_to_shared(&Al[0][0]);
    const uint32_t sBh = (uint32_t)__cvta_generic_to_shared(&Bh[0][0]);
    const uint32_t sBl = (uint32_t)__cvta_generic_to_shared(&Bl[0][0]);
    const uint32_t laneOff = (uint32_t)(rowo * 40 + col8) * 2;

    float acc[4][4][4];
#pragma unroll
    for (int a = 0; a < 4; a++)
#pragma unroll
        for (int b = 0; b < 4; b++)
#pragma unroll
            for (int c = 0; c < 4; c++) acc[a][b][c] = 0.f;

    for (int k0 = 0; k0 < KF; k0 += 32) {
#pragma unroll
        for (int u = t; u < 512; u += 256) {
            int r = u >> 2, cg = (u & 3) * 8;
            uint4 vh = make_uint4(0, 0, 0, 0), vl = vh;
            int gm = bm + r;
            if (gm < NN) {
                vh = *(const uint4*)&g_Ahi[(size_t)gm * KF + k0 + cg];
                vl = *(const uint4*)&g_Alo[(size_t)gm * KF + k0 + cg];
            }
            *(uint4*)&Ah[r][cg] = vh;
            *(uint4*)&Al[r][cg] = vl;
            *(uint4*)&Bh[r][cg] = *(const uint4*)&Bhi[(size_t)(bn + r) * KF + k0 + cg];
            *(uint4*)&Bl[r][cg] = *(const uint4*)&Blo[(size_t)(bn + r) * KF + k0 + cg];
        }
        __syncthreads();
#pragma unroll
        for (int kk = 0; kk < 32; kk += 16) {
            uint32_t ah[4][4], al[4][4];
#pragma unroll
            for (int mt = 0; mt < 4; mt++) {
                uint32_t rowBase = (uint32_t)((wr + mt * 16) * 40 + kk) * 2 + laneOff;
                ldsm_x4(ah[mt][0], ah[mt][1], ah[mt][2], ah[mt][3], sAh + rowBase);
                ldsm_x4(al[mt][0], al[mt][1], al[mt][2], al[mt][3], sAl + rowBase);
            }
            uint32_t bh[4][2], bl[4][2];
#pragma unroll
            for (int p = 0; p < 2; p++) {
                uint32_t colBase = (uint32_t)((wc + p * 16) * 40 + kk) * 2 + laneOff;
                ldsm_x4(bh[2 * p][0], bh[2 * p + 1][0], bh[2 * p][1], bh[2 * p + 1][1],
                        sBh + colBase);
                ldsm_x4(bl[2 * p][0], bl[2 * p + 1][0], bl[2 * p][1], bl[2 * p + 1][1],
                        sBl + colBase);
            }
#pragma unroll
            for (int nt = 0; nt < 4; nt++) {
#pragma unroll
                for (int mt = 0; mt < 4; mt++) {
                    mma16816(acc[mt][nt], ah[mt], bh[nt][0], bh[nt][1]);
                    mma16816(acc[mt][nt], ah[mt], bl[nt][0], bl[nt][1]);
                    mma16816(acc[mt][nt], al[mt], bh[nt][0], bh[nt][1]);
                }
            }
        }
        __syncthreads();
    }

    // ---- epilogue: fp16 store + per-row alpha partials ----
#pragma unroll
    for (int mt = 0; mt < 4; mt++) {
        int r0 = bm + wr + mt * 16 + g;
        float pa0 = 0.f, pd0 = 0.f, pa8 = 0.f, pd8 = 0.f;
#pragma unroll
        for (int nt = 0; nt < 4; nt++) {
            int lc = wc + nt * 8 + tg;
            float s0 = as_s[lc], s1 = as_s[lc + 1];
            float d0v = ad_s[lc], d1v = ad_s[lc + 1];
            pa0 = fmaf(acc[mt][nt][0], s0, fmaf(acc[mt][nt][1], s1, pa0));
            pd0 = fmaf(acc[mt][nt][0], d0v, fmaf(acc[mt][nt][1], d1v, pd0));
            pa8 = fmaf(acc[mt][nt][2], s0, fmaf(acc[mt][nt][3], s1, pa8));
            pd8 = fmaf(acc[mt][nt][2], d0v, fmaf(acc[mt][nt][3], d1v, pd8));
            if (r0 < NN)
                *(__half2*)&g_hh[(size_t)r0 * HC + bn + lc] =
                    __floats2half2_rn(acc[mt][nt][0], acc[mt][nt][1]);
            if (r0 + 8 < NN)
                *(__half2*)&g_hh[(size_t)(r0 + 8) * HC + bn + lc] =
                    __floats2half2_rn(acc[mt][nt][2], acc[mt][nt][3]);
        }
#pragma unroll
        for (int off = 1; off < 4; off <<= 1) {
            pa0 += __shfl_xor_sync(0xffffffffu, pa0, off);
            pd0 += __shfl_xor_sync(0xffffffffu, pd0, off);
            pa8 += __shfl_xor_sync(0xffffffffu, pa8, off);
            pd8 += __shfl_xor_sync(0xffffffffu, pd8, off);
        }
        if ((lane & 3) == 0) {
            int rl = mt * 16 + g;
            part_as[warp][rl]     = pa0;
            part_as[warp][rl + 8] = pa8;
            part_ad[warp][rl]     = pd0;
            part_ad[warp][rl + 8] = pd8;
        }
    }
    __syncthreads();
    {
        int r  = t & 127;            // local row
        int hl = t >> 7;             // local head 0/1
        int p  = (r >= 64) ? 1 : 0;
        int rl = r & 63;
        int w0 = p + hl * 4, w1 = p + 2 + hl * 4;
        if (bm + r < NN) {
            int hg = (bn >> 6) + hl;     // global head
            g_as[(bm + r) * 4 + hg] = part_as[w0][rl] + part_as[w1][rl];
            g_ad[(bm + r) * 4 + hg] = part_ad[w0][rl] + part_ad[w1][rl];
        }
    }
}

// ---------------- aggregation ----------------
__device__ __forceinline__ void fma8(float* acc, float wl, uint4 u) {
    union { uint4 uu; __half2 h[4]; } H; H.uu = u;
    float2 f0 = __half22float2(H.h[0]);
    float2 f1 = __half22float2(H.h[1]);
    float2 f2 = __half22float2(H.h[2]);
    float2 f3 = __half22float2(H.h[3]);
    acc[0] = fmaf(wl, f0.x, acc[0]); acc[1] = fmaf(wl, f0.y, acc[1]);
    acc[2] = fmaf(wl, f1.x, acc[2]); acc[3] = fmaf(wl, f1.y, acc[3]);
    acc[4] = fmaf(wl, f2.x, acc[4]); acc[5] = fmaf(wl, f2.y, acc[5]);
    acc[6] = fmaf(wl, f3.x, acc[6]); acc[7] = fmaf(wl, f3.y, acc[7]);
}

template <bool TO_OUT>
__global__ void k_aggregate(const float* __restrict__ bias, float* __restrict__ out) {
    int warp = (blockIdx.x * blockDim.x + threadIdx.x) >> 5;
    if (warp >= NN) return;
    const int n = warp;
    const int l = threadIdx.x & 31;
    const int beg = g_rowptr[n];
    const int dr  = g_rowptr[n + 1] - beg;       // real edges; self handled logically
    const float4 adn = *(const float4*)&g_ad[n * 4];
    const float4 asn = *(const float4*)&g_as[n * 4];

    float4 ws;   // self-loop weight (logits O(1) bounded; no max-shift needed)
    ws.x = __expf(lrelu(asn.x + adn.x)); ws.y = __expf(lrelu(asn.y + adn.y));
    ws.z = __expf(lrelu(asn.z + adn.z)); ws.w = __expf(lrelu(asn.w + adn.w));

    float d0 = 0.f, d1 = 0.f, d2 = 0.f, d3 = 0.f;
    for (int i = l; i < dr; i += 32) {
        int s = g_csr[beg + i];
        float4 av = *(const float4*)&g_as[s * 4];
        float4 w;
        w.x = __expf(lrelu(av.x + adn.x)); w.y = __expf(lrelu(av.y + adn.y));
        w.z = __expf(lrelu(av.z + adn.z)); w.w = __expf(lrelu(av.w + adn.w));
        g_w4[beg + i] = w;
        d0 += w.x; d1 += w.y; d2 += w.z; d3 += w.w;
    }
#pragma unroll
    for (int off = 16; off; off >>= 1) {
        d0 += __shfl_xor_sync(0xffffffffu, d0, off);
        d1 += __shfl_xor_sync(0xffffffffu, d1, off);
        d2 += __shfl_xor_sync(0xffffffffu, d2, off);
        d3 += __shfl_xor_sync(0xffffffffu, d3, off);
    }
    d0 += ws.x; d1 += ws.y; d2 += ws.z; d3 += ws.w;
    const float r0 = 1.f / (d0 + 1e-16f), r1 = 1.f / (d1 + 1e-16f);
    const float r2 = 1.f / (d2 + 1e-16f), r3 = 1.f / (d3 + 1e-16f);
    __syncwarp();

    // pass C: fp16 weighted gather, unrolled x4 for MLP.
    const int hd = l >> 3;
    const float rh = (hd == 0) ? r0 : (hd == 1) ? r1 : (hd == 2) ? r2 : r3;
    const int c8 = 8 * l;
    float acc[8];
#pragma unroll
    for (int j = 0; j < 8; j++) acc[j] = 0.f;

    int i = 0;
    for (; i + 4 <= dr; i += 4) {
        int s0 = g_csr[beg + i + 0], s1 = g_csr[beg + i + 1];
        int s2 = g_csr[beg + i + 2], s3 = g_csr[beg + i + 3];
        float4 w0 = g_w4[beg + i + 0], w1 = g_w4[beg + i + 1];
        float4 w2 = g_w4[beg + i + 2], w3 = g_w4[beg + i + 3];
        uint4 u0 = *(const uint4*)&g_hh[(size_t)s0 * HC + c8];
        uint4 u1 = *(const uint4*)&g_hh[(size_t)s1 * HC + c8];
        uint4 u2 = *(const uint4*)&g_hh[(size_t)s2 * HC + c8];
        uint4 u3 = *(const uint4*)&g_hh[(size_t)s3 * HC + c8];
        float wl0 = ((hd == 0) ? w0.x : (hd == 1) ? w0.y : (hd == 2) ? w0.z : w0.w) * rh;
        float wl1 = ((hd == 0) ? w1.x : (hd == 1) ? w1.y : (hd == 2) ? w1.z : w1.w) * rh;
        float wl2 = ((hd == 0) ? w2.x : (hd == 1) ? w2.y : (hd == 2) ? w2.z : w2.w) * rh;
        float wl3 = ((hd == 0) ? w3.x : (hd == 1) ? w3.y : (hd == 2) ? w3.z : w3.w) * rh;
        fma8(acc, wl0, u0); fma8(acc, wl1, u1);
        fma8(acc, wl2, u2); fma8(acc, wl3, u3);
    }
    for (; i < dr; i++) {
        int s = g_csr[beg + i];
        float4 w = g_w4[beg + i];
        uint4 u = *(const uint4*)&g_hh[(size_t)s * HC + c8];
        float wl = ((hd == 0) ? w.x : (hd == 1) ? w.y : (hd == 2) ? w.z : w.w) * rh;
        fma8(acc, wl, u);
    }
    {   // self loop
        float wl = ((hd == 0) ? ws.x : (hd == 1) ? ws.y : (hd == 2) ? ws.z : ws.w) * rh;
        uint4 u = *(const uint4*)&g_hh[(size_t)n * HC + c8];
        fma8(acc, wl, u);
    }
#pragma unroll
    for (int j = 0; j < 8; j++) {
        acc[j] += __shfl_xor_sync(0xffffffffu, acc[j], 8);
        acc[j] += __shfl_xor_sync(0xffffffffu, acc[j], 16);
    }
    if (l < 8) {
        const float4 ba = *(const float4*)&bias[8 * l];
        const float4 bb = *(const float4*)&bias[8 * l + 4];
        float o[8];
#pragma unroll
        for (int j = 0; j < 8; j++) o[j] = acc[j] * 0.25f;
        o[0] += ba.x; o[1] += ba.y; o[2] += ba.z; o[3] += ba.w;
        o[4] += bb.x; o[5] += bb.y; o[6] += bb.z; o[7] += bb.w;
        if (!TO_OUT) {
            union { __nv_bfloat16 b[8]; uint4 u; } Hh, Hl;
#pragma unroll
            for (int j = 0; j < 8; j++) {
                float v = o[j] > 0.f ? o[j] : expm1f(o[j]);
                __nv_bfloat16 hb = __float2bfloat16_rn(v);
                Hh.b[j] = hb;
                Hl.b[j] = __float2bfloat16_rn(v - __bfloat162float(hb));
            }
            *(uint4*)&g_Ahi[(size_t)n * HF + 8 * l] = Hh.u;
            *(uint4*)&g_Alo[(size_t)n * HF + 8 * l] = Hl.u;
        } else {
            *(float4*)&out[(size_t)n * HF + 8 * l]     = make_float4(o[0], o[1], o[2], o[3]);
            *(float4*)&out[(size_t)n * HF + 8 * l + 4] = make_float4(o[4], o[5], o[6], o[7]);
        }
    }
}

// ---------------- host launcher ----------------
extern "C" void kernel_launch(void* const* d_in, const int* in_sizes, int n_in,
                              void* d_out, int out_size) {
    const float* x   = (const float*)d_in[0];
    const void*  ei  = d_in[1];
    const float* W1  = (const float*)d_in[2];
    const float* as1 = (const float*)d_in[3];
    const float* ad1 = (const float*)d_in[4];
    const float* b1  = (const float*)d_in[5];
    const float* W2  = (const float*)d_in[6];
    const float* as2 = (const float*)d_in[7];
    const float* ad2 = (const float*)d_in[8];
    const float* b2  = (const float*)d_in[9];
    float*       out = (float*)d_out;

    const int warps_grid = (NN * 32 + 255) / 256;

    k_prep<<<64, 256>>>((const long long*)ei, W1, W2);            // probe, W cvt, flag clear
    k_hist_cvt<<<HIST_BLOCKS + XCVT_BLOCKS, 256>>>(ei, x);        // hist + x cvt concurrent
    k_scan1<<<NBLK, 256>>>();                                     // single-pass lookback scan

    // layer 1: GEMM + alpha epilogue, with grid-stride CSR scatter fused in
    k_mma<IN_F, 1, true><<<GEMM_BLOCKS + SCATTER_BLOCKS, 256>>>(as1, ad1, ei);
    k_aggregate<false><<<warps_grid, 256>>>(b1, nullptr);         // writes split-bf16 A

    // layer 2
    k_mma<HF, 2, false><<<GEMM_BLOCKS, 256>>>(as2, ad2, ei);
    k_aggregate<true><<<warps_grid, 256>>>(b2, out);
}

// round 16
// speedup vs baseline: 2.0256x; 1.1828x over previous
#include <cuda_runtime.h>
#include <cuda_fp16.h>
#include <cstdint>

#define NN 50000
#define EE 800000
#define IN_F 128
#define HF 64
#define HEADS 4
#define HC 256            // HEADS*HF
#define NEG_SLOPE 0.2f
#define NBLK ((NN + 255) / 256)         // 196
#define HIST_BLOCKS ((EE + 255) / 256)  // 3125
#define XCVT_BLOCKS ((NN * IN_F / 4 + 255) / 256)  // 6250
#define GEMM_BLOCKS (((NN + 127) / 128) * 2)       // 782
#define SCATTER_BLOCKS 600
#define ABUF (128 * 40 * 2)             // one smem tile buffer in bytes

// ---------------- device scratch ----------------
__device__ __align__(16) __half g_hh[(size_t)NN * HC];    // fp16 features for gather
__device__ __align__(16) float g_as[NN * HEADS];
__device__ __align__(16) float g_ad[NN * HEADS];
__device__ __align__(16) float4 g_w4[EE];                 // per-edge softmax weights
__device__ __align__(16) __half g_A[(size_t)NN * IN_F];   // GEMM A operand (fp16)
__device__ __align__(16) __half g_B1[HC * IN_F];
__device__ __align__(16) __half g_B2[HC * HF];
__device__ int   g_deg[NN];              // static zero; re-zeroed by k_scan1 each launch
__device__ int   g_rowptr[NN + 1];
__device__ int   g_cursor[NN];
__device__ int   g_csr[EE];
__device__ unsigned long long g_look[NBLK];  // lookback descriptors; cleared by k_prep
__device__ int   g_is64 = 1;             // probes only ever write 0 (deterministic)

__device__ __forceinline__ float lrelu(float v) { return v > 0.f ? v : NEG_SLOPE * v; }

// convert one float4 into 4 fp16 at element index 4*i (8B store)
__device__ __forceinline__ void cvt4h(float4 v, __half* dst, int i) {
    union { __half2 h[2]; uint2 u; } P;
    P.h[0] = __floats2half2_rn(v.x, v.y);
    P.h[1] = __floats2half2_rn(v.z, v.w);
    *(uint2*)&dst[4 * i] = P.u;
}

// ---------------- prep: dtype probe + W1/W2 cvt + lookback-flag clear ----------
__global__ void k_prep(const long long* __restrict__ ei,
                       const float* __restrict__ W1, const float* __restrict__ W2) {
    int i = blockIdx.x * blockDim.x + threadIdx.x;
    if (i < 4096) {                       // sampled dtype probe
        long long v = ei[(size_t)i * 195];
        if (v < 0 || v >= NN) g_is64 = 0;
    }
    if (i < NBLK) g_look[i] = 0ULL;       // reset lookback state for this launch
    if (i < HC * IN_F / 4) cvt4h(((const float4*)W1)[i], g_B1, i);
    if (i < HC * HF / 4)   cvt4h(((const float4*)W2)[i], g_B2, i);
}

// histogram (blocks [0,HIST_BLOCKS)) + x -> fp16 (remaining blocks)
__global__ void k_hist_cvt(const void* __restrict__ eiv, const float* __restrict__ x) {
    if (blockIdx.x < HIST_BLOCKS) {
        int e = blockIdx.x * 256 + threadIdx.x;
        if (e < EE) {
            int d = g_is64 ? (int)((const long long*)eiv)[EE + e]
                           : ((const int*)eiv)[EE + e];
            if ((unsigned)d < NN) atomicAdd(&g_deg[d], 1);
        }
    } else {
        int i = (blockIdx.x - HIST_BLOCKS) * 256 + threadIdx.x;
        if (i < NN * IN_F / 4) cvt4h(((const float4*)x)[i], g_A, i);
    }
}

// ---------------- single-pass decoupled-lookback scan ----------------
__global__ void __launch_bounds__(256) k_scan1() {
    __shared__ int sm[256];
    __shared__ int s_pfx;
    const int b = blockIdx.x, t = threadIdx.x;
    const int i = b * 256 + t;
    int v = (i < NN) ? g_deg[i] : 0;
    if (i < NN) g_deg[i] = 0;            // re-zero for next graph replay
    sm[t] = v;
    __syncthreads();
#pragma unroll
    for (int off = 1; off < 256; off <<= 1) {
        int x = (t >= off) ? sm[t - off] : 0;
        __syncthreads();
        sm[t] += x;
        __syncthreads();
    }
    const int total = sm[255];

    if (b == 0) {
        if (t == 0) {
            s_pfx = 0;
            atomicExch(&g_look[0], (2ULL << 32) | (unsigned)total);
        }
    } else {
        if (t == 0)
            atomicExch(&g_look[b], (1ULL << 32) | (unsigned)total);
        if (t < 32) {                                   // warp-parallel lookback
            int pfx = 0;
            int base = b - 1;
            while (true) {
                int j = base - t;
                unsigned long long d = (j >= 0)
                    ? atomicAdd(&g_look[j], 0ULL)
                    : (2ULL << 32);
                unsigned f = (unsigned)(d >> 32);
                unsigned bal2 = __ballot_sync(0xffffffffu, f == 2);
                unsigned bal0 = __ballot_sync(0xffffffffu, f == 0);
                if (bal0 == 0) {
                    if (bal2) {
                        int L = __ffs(bal2) - 1;
                        int val = (t <= L) ? (int)(unsigned)d : 0;
#pragma unroll
                        for (int o = 16; o; o >>= 1) val += __shfl_xor_sync(0xffffffffu, val, o);
                        pfx += val;
                        break;
                    } else {
                        int val = (int)(unsigned)d;
#pragma unroll
                        for (int o = 16; o; o >>= 1) val += __shfl_xor_sync(0xffffffffu, val, o);
                        pfx += val;
                        base -= 32;
                    }
                }
            }
            if (t == 0) {
                s_pfx = pfx;
                atomicExch(&g_look[b], (2ULL << 32) | (unsigned)(total + pfx));
            }
        }
    }
    __syncthreads();
    const int pfx = s_pfx;
    if (i < NN) {
        int excl = pfx + sm[t] - v;
        g_rowptr[i] = excl;
        g_cursor[i] = excl;
    }
    if (i == NN - 1) g_rowptr[NN] = pfx + sm[t];
}

// ---------------- tensor-core GEMM (fp16) + fused alpha/fp16 epilogue ----------
__device__ __forceinline__ void mma16816(float* c, const uint32_t* a, uint32_t b0, uint32_t b1) {
    asm volatile(
        "mma.sync.aligned.m16n8k16.row.col.f32.f16.f16.f32 "
        "{%0,%1,%2,%3},{%4,%5,%6,%7},{%8,%9},{%0,%1,%2,%3};"
        : "+f"(c[0]), "+f"(c[1]), "+f"(c[2]), "+f"(c[3])
        : "r"(a[0]), "r"(a[1]), "r"(a[2]), "r"(a[3]), "r"(b0), "r"(b1));
}

__device__ __forceinline__ void ldsm_x4(uint32_t& r0, uint32_t& r1, uint32_t& r2, uint32_t& r3,
                                        uint32_t addr) {
    asm volatile("ldmatrix.sync.aligned.m8n8.x4.shared.b16 {%0,%1,%2,%3}, [%4];"
                 : "=r"(r0), "=r"(r1), "=r"(r2), "=r"(r3) : "r"(addr));
}

__device__ __forceinline__ void cp16(uint32_t dst, const void* src, bool pred) {
    asm volatile("cp.async.ca.shared.global [%0], [%1], 16, %2;"
                 :: "r"(dst), "l"(src), "r"(pred ? 16 : 0));
}

template <int KF, int LAYER, bool FUSE_SCATTER>
__global__ void __launch_bounds__(256) k_mma(const float* __restrict__ a_src,
                                             const float* __restrict__ a_dst,
                                             const void* __restrict__ eiv) {
    __shared__ __align__(16) __half Ah[2][128][40];   // double-buffered
    __shared__ __align__(16) __half Bh[2][128][40];
    __shared__ float as_s[128], ad_s[128];
    __shared__ float part_as[8][64], part_ad[8][64];

    if (FUSE_SCATTER && blockIdx.x >= GEMM_BLOCKS) {     // concurrent grid-stride scatter
        for (int e = (blockIdx.x - GEMM_BLOCKS) * 256 + threadIdx.x; e < EE;
             e += SCATTER_BLOCKS * 256) {
            int s, d;
            if (g_is64) {
                s = (int)((const long long*)eiv)[e];
                d = (int)((const long long*)eiv)[EE + e];
            } else {
                s = ((const int*)eiv)[e];
                d = ((const int*)eiv)[EE + e];
            }
            if ((unsigned)s < NN && (unsigned)d < NN) {
                int p = atomicAdd(&g_cursor[d], 1);
                g_csr[p] = s;
            }
        }
        return;
    }

    const __half* Bp = (LAYER == 1) ? g_B1 : g_B2;
    const int t = threadIdx.x;
    const int bm = (blockIdx.x >> 1) * 128, bn = (blockIdx.x & 1) * 128;
    const int warp = t >> 5, lane = t & 31;
    const int wr = (warp & 1) * 64, wc = (warp >> 1) * 32;
    const int g = lane >> 2, tg = (lane & 3) * 2;

    if (t < 128) {
        as_s[t] = a_src[bn + t];
        ad_s[t] = a_dst[bn + t];
    }

    const int rowo = lane & 15;
    const int col8 = (lane & 16) >> 1;
    const uint32_t sAh = (uint32_t)__cvta_generic_to_shared(&Ah[0][0][0]);
    const uint32_t sBh = (uint32_t)__cvta_generic_to_shared(&Bh[0][0][0]);
    const uint32_t laneOff = (uint32_t)(rowo * 40 + col8) * 2;

    // cp.async load of one 128x32 fp16 tile pair into buffer `buf`
    const int r0l = t >> 2, cgl = (t & 3) * 8;       // each thread: rows r0l, r0l+64
    auto issue_tile = [&](int k0, int buf) {
        uint32_t aB = sAh + buf * ABUF, bB = sBh + buf * ABUF;
#pragma unroll
        for (int rr = 0; rr < 2; rr++) {
            int r = r0l + rr * 64;
            cp16(aB + (uint32_t)(r * 40 + cgl) * 2,
                 &g_A[(size_t)(bm + r) * KF + k0 + cgl], bm + r < NN);
            cp16(bB + (uint32_t)(r * 40 + cgl) * 2,
                 &Bp[(size_t)(bn + r) * KF + k0 + cgl], true);
        }
        asm volatile("cp.async.commit_group;");
    };

    float acc[4][4][4];
#pragma unroll
    for (int a = 0; a < 4; a++)
#pragma unroll
        for (int b = 0; b < 4; b++)
#pragma unroll
            for (int c = 0; c < 4; c++) acc[a][b][c] = 0.f;

    issue_tile(0, 0);
#pragma unroll
    for (int k0 = 0; k0 < KF; k0 += 32) {
        const int buf = (k0 >> 5) & 1;
        if (k0 + 32 < KF) {
            issue_tile(k0 + 32, buf ^ 1);
            asm volatile("cp.async.wait_group 1;");
        } else {
            asm volatile("cp.async.wait_group 0;");
        }
        __syncthreads();
        const uint32_t aB = sAh + buf * ABUF, bB = sBh + buf * ABUF;
#pragma unroll
        for (int kk = 0; kk < 32; kk += 16) {
            uint32_t ah[4][4];
#pragma unroll
            for (int mt = 0; mt < 4; mt++) {
                uint32_t rowBase = (uint32_t)((wr + mt * 16) * 40 + kk) * 2 + laneOff;
                ldsm_x4(ah[mt][0], ah[mt][1], ah[mt][2], ah[mt][3], aB + rowBase);
            }
            uint32_t bh[4][2];
#pragma unroll
            for (int p = 0; p < 2; p++) {
                uint32_t colBase = (uint32_t)((wc + p * 16) * 40 + kk) * 2 + laneOff;
                ldsm_x4(bh[2 * p][0], bh[2 * p + 1][0], bh[2 * p][1], bh[2 * p + 1][1],
                        bB + colBase);
            }
#pragma unroll
            for (int nt = 0; nt < 4; nt++)
#pragma unroll
                for (int mt = 0; mt < 4; mt++)
                    mma16816(acc[mt][nt], ah[mt], bh[nt][0], bh[nt][1]);
        }
        __syncthreads();
    }

    // ---- epilogue: fp16 store + per-row alpha partials ----
#pragma unroll
    for (int mt = 0; mt < 4; mt++) {
        int r0 = bm + wr + mt * 16 + g;
        float pa0 = 0.f, pd0 = 0.f, pa8 = 0.f, pd8 = 0.f;
#pragma unroll
        for (int nt = 0; nt < 4; nt++) {
            int lc = wc + nt * 8 + tg;
            float s0 = as_s[lc], s1 = as_s[lc + 1];
            float d0v = ad_s[lc], d1v = ad_s[lc + 1];
            pa0 = fmaf(acc[mt][nt][0], s0, fmaf(acc[mt][nt][1], s1, pa0));
            pd0 = fmaf(acc[mt][nt][0], d0v, fmaf(acc[mt][nt][1], d1v, pd0));
            pa8 = fmaf(acc[mt][nt][2], s0, fmaf(acc[mt][nt][3], s1, pa8));
            pd8 = fmaf(acc[mt][nt][2], d0v, fmaf(acc[mt][nt][3], d1v, pd8));
            if (r0 < NN)
                *(__half2*)&g_hh[(size_t)r0 * HC + bn + lc] =
                    __floats2half2_rn(acc[mt][nt][0], acc[mt][nt][1]);
            if (r0 + 8 < NN)
                *(__half2*)&g_hh[(size_t)(r0 + 8) * HC + bn + lc] =
                    __floats2half2_rn(acc[mt][nt][2], acc[mt][nt][3]);
        }
#pragma unroll
        for (int off = 1; off < 4; off <<= 1) {
            pa0 += __shfl_xor_sync(0xffffffffu, pa0, off);
            pd0 += __shfl_xor_sync(0xffffffffu, pd0, off);
            pa8 += __shfl_xor_sync(0xffffffffu, pa8, off);
            pd8 += __shfl_xor_sync(0xffffffffu, pd8, off);
        }
        if ((lane & 3) == 0) {
            int rl = mt * 16 + g;
            part_as[warp][rl]     = pa0;
            part_as[warp][rl + 8] = pa8;
            part_ad[warp][rl]     = pd0;
            part_ad[warp][rl + 8] = pd8;
        }
    }
    __syncthreads();
    {
        int r  = t & 127;            // local row
        int hl = t >> 7;             // local head 0/1
        int p  = (r >= 64) ? 1 : 0;
        int rl = r & 63;
        int w0 = p + hl * 4, w1 = p + 2 + hl * 4;
        if (bm + r < NN) {
            int hg = (bn >> 6) + hl;     // global head
            g_as[(bm + r) * 4 + hg] = part_as[w0][rl] + part_as[w1][rl];
            g_ad[(bm + r) * 4 + hg] = part_ad[w0][rl] + part_ad[w1][rl];
        }
    }
}

// ---------------- aggregation ----------------
__device__ __forceinline__ void fma8(float* acc, float wl, uint4 u) {
    union { uint4 uu; __half2 h[4]; } H; H.uu = u;
    float2 f0 = __half22float2(H.h[0]);
    float2 f1 = __half22float2(H.h[1]);
    float2 f2 = __half22float2(H.h[2]);
    float2 f3 = __half22float2(H.h[3]);
    acc[0] = fmaf(wl, f0.x, acc[0]); acc[1] = fmaf(wl, f0.y, acc[1]);
    acc[2] = fmaf(wl, f1.x, acc[2]); acc[3] = fmaf(wl, f1.y, acc[3]);
    acc[4] = fmaf(wl, f2.x, acc[4]); acc[5] = fmaf(wl, f2.y, acc[5]);
    acc[6] = fmaf(wl, f3.x, acc[6]); acc[7] = fmaf(wl, f3.y, acc[7]);
}

// TO_OUT=false: layer 1 -> ELU, write fp16 into g_A (HF cols). TO_OUT=true: output.
template <bool TO_OUT>
__global__ void k_aggregate(const float* __restrict__ bias, float* __restrict__ out) {
    int warp = (blockIdx.x * blockDim.x + threadIdx.x) >> 5;
    if (warp >= NN) return;
    const int n = warp;
    const int l = threadIdx.x & 31;
    const int beg = g_rowptr[n];
    const int dr  = g_rowptr[n + 1] - beg;       // real edges; self handled logically
    const float4 adn = *(const float4*)&g_ad[n * 4];
    const float4 asn = *(const float4*)&g_as[n * 4];

    float4 ws;   // self-loop weight (logits O(1) bounded; no max-shift needed)
    ws.x = __expf(lrelu(asn.x + adn.x)); ws.y = __expf(lrelu(asn.y + adn.y));
    ws.z = __expf(lrelu(asn.z + adn.z)); ws.w = __expf(lrelu(asn.w + adn.w));

    float d0 = 0.f, d1 = 0.f, d2 = 0.f, d3 = 0.f;
    for (int i = l; i < dr; i += 32) {
        int s = g_csr[beg + i];
        float4 av = *(const float4*)&g_as[s * 4];
        float4 w;
        w.x = __expf(lrelu(av.x + adn.x)); w.y = __expf(lrelu(av.y + adn.y));
        w.z = __expf(lrelu(av.z + adn.z)); w.w = __expf(lrelu(av.w + adn.w));
        g_w4[beg + i] = w;
        d0 += w.x; d1 += w.y; d2 += w.z; d3 += w.w;
    }
#pragma unroll
    for (int off = 16; off; off >>= 1) {
        d0 += __shfl_xor_sync(0xffffffffu, d0, off);
        d1 += __shfl_xor_sync(0xffffffffu, d1, off);
        d2 += __shfl_xor_sync(0xffffffffu, d2, off);
        d3 += __shfl_xor_sync(0xffffffffu, d3, off);
    }
    d0 += ws.x; d1 += ws.y; d2 += ws.z; d3 += ws.w;
    const float r0 = 1.f / (d0 + 1e-16f), r1 = 1.f / (d1 + 1e-16f);
    const float r2 = 1.f / (d2 + 1e-16f), r3 = 1.f / (d3 + 1e-16f);
    __syncwarp();

    // pass C: fp16 weighted gather, unrolled x4 for MLP.
    const int hd = l >> 3;
    const float rh = (hd == 0) ? r0 : (hd == 1) ? r1 : (hd == 2) ? r2 : r3;
    const int c8 = 8 * l;
    float acc[8];
#pragma unroll
    for (int j = 0; j < 8; j++) acc[j] = 0.f;

    int i = 0;
    for (; i + 4 <= dr; i += 4) {
        int s0 = g_csr[beg + i + 0], s1 = g_csr[beg + i + 1];
        int s2 = g_csr[beg + i + 2], s3 = g_csr[beg + i + 3];
        float4 w0 = g_w4[beg + i + 0], w1 = g_w4[beg + i + 1];
        float4 w2 = g_w4[beg + i + 2], w3 = g_w4[beg + i + 3];
        uint4 u0 = *(const uint4*)&g_hh[(size_t)s0 * HC + c8];
        uint4 u1 = *(const uint4*)&g_hh[(size_t)s1 * HC + c8];
        uint4 u2 = *(const uint4*)&g_hh[(size_t)s2 * HC + c8];
        uint4 u3 = *(const uint4*)&g_hh[(size_t)s3 * HC + c8];
        float wl0 = ((hd == 0) ? w0.x : (hd == 1) ? w0.y : (hd == 2) ? w0.z : w0.w) * rh;
        float wl1 = ((hd == 0) ? w1.x : (hd == 1) ? w1.y : (hd == 2) ? w1.z : w1.w) * rh;
        float wl2 = ((hd == 0) ? w2.x : (hd == 1) ? w2.y : (hd == 2) ? w2.z : w2.w) * rh;
        float wl3 = ((hd == 0) ? w3.x : (hd == 1) ? w3.y : (hd == 2) ? w3.z : w3.w) * rh;
        fma8(acc, wl0, u0); fma8(acc, wl1, u1);
        fma8(acc, wl2, u2); fma8(acc, wl3, u3);
    }
    for (; i < dr; i++) {
        int s = g_csr[beg + i];
        float4 w = g_w4[beg + i];
        uint4 u = *(const uint4*)&g_hh[(size_t)s * HC + c8];
        float wl = ((hd == 0) ? w.x : (hd == 1) ? w.y : (hd == 2) ? w.z : w.w) * rh;
        fma8(acc, wl, u);
    }
    {   // self loop
        float wl = ((hd == 0) ? ws.x : (hd == 1) ? ws.y : (hd == 2) ? ws.z : ws.w) * rh;
        uint4 u = *(const uint4*)&g_hh[(size_t)n * HC + c8];
        fma8(acc, wl, u);
    }
#pragma unroll
    for (int j = 0; j < 8; j++) {
        acc[j] += __shfl_xor_sync(0xffffffffu, acc[j], 8);
        acc[j] += __shfl_xor_sync(0xffffffffu, acc[j], 16);
    }
    if (l < 8) {
        const float4 ba = *(const float4*)&bias[8 * l];
        const float4 bb = *(const float4*)&bias[8 * l + 4];
        float o[8];
#pragma unroll
        for (int j = 0; j < 8; j++) o[j] = acc[j] * 0.25f;
        o[0] += ba.x; o[1] += ba.y; o[2] += ba.z; o[3] += ba.w;
        o[4] += bb.x; o[5] += bb.y; o[6] += bb.z; o[7] += bb.w;
        if (!TO_OUT) {
            // ELU + fp16 store straight into layer-2's A operand
            union { __half2 h[4]; uint4 u; } Hh;
#pragma unroll
            for (int j = 0; j < 4; j++) {
                float v0 = o[2 * j]     > 0.f ? o[2 * j]     : expm1f(o[2 * j]);
                float v1 = o[2 * j + 1] > 0.f ? o[2 * j + 1] : expm1f(o[2 * j + 1]);
                Hh.h[j] = __floats2half2_rn(v0, v1);
            }
            *(uint4*)&g_A[(size_t)n * HF + 8 * l] = Hh.u;
        } else {
            *(float4*)&out[(size_t)n * HF + 8 * l]     = make_float4(o[0], o[1], o[2], o[3]);
            *(float4*)&out[(size_t)n * HF + 8 * l + 4] = make_float4(o[4], o[5], o[6], o[7]);
        }
    }
}

// ---------------- host launcher ----------------
extern "C" void kernel_launch(void* const* d_in, const int* in_sizes, int n_in,
                              void* d_out, int out_size) {
    const float* x   = (const float*)d_in[0];
    const void*  ei  = d_in[1];
    const float* W1  = (const float*)d_in[2];
    const float* as1 = (const float*)d_in[3];
    const float* ad1 = (const float*)d_in[4];
    const float* b1  = (const float*)d_in[5];
    const float* W2  = (const float*)d_in[6];
    const float* as2 = (const float*)d_in[7];
    const float* ad2 = (const float*)d_in[8];
    const float* b2  = (const float*)d_in[9];
    float*       out = (float*)d_out;

    const int warps_grid = (NN * 32 + 255) / 256;

    k_prep<<<64, 256>>>((const long long*)ei, W1, W2);            // probe, W cvt, flag clear
    k_hist_cvt<<<HIST_BLOCKS + XCVT_BLOCKS, 256>>>(ei, x);        // hist + x cvt concurrent
    k_scan1<<<NBLK, 256>>>();                                     // single-pass lookback scan

    // layer 1: GEMM + alpha epilogue, with grid-stride CSR scatter fused in
    k_mma<IN_F, 1, true><<<GEMM_BLOCKS + SCATTER_BLOCKS, 256>>>(as1, ad1, ei);
    k_aggregate<false><<<warps_grid, 256>>>(b1, nullptr);         // writes fp16 A

    // layer 2
    k_mma<HF, 2, false><<<GEMM_BLOCKS, 256>>>(as2, ad2, ei);
    k_aggregate<true><<<warps_grid, 256>>>(b2, out);
}